// round 11
// baseline (speedup 1.0000x reference)
#include <cuda_runtime.h>
#include <cstdint>

#define B_   2
#define C_   256
#define MLOC 16384   // NW*64 local tokens per batch
#define MQ   4096    // NW*16 query tokens per batch
#define MG   1280    // 1024 mid + 256 glb tokens per batch
#define NW   256
#define LK   1344

typedef unsigned long long u64;

// ---------------- scratch (device globals; ONLY referenced from device code) ----------------
__device__ float g_tq   [B_ * MQ * C_];
__device__ float g_tloc [(size_t)B_ * MLOC * C_];
__device__ float g_tmg  [B_ * MG * C_];
__device__ float g_q    [B_ * MQ * C_];
__device__ float g_kvloc[(size_t)B_ * MLOC * 512];  // K+bias:0..255, V+bias:256..511
__device__ float g_kvmg [B_ * MG * 512];
__device__ float g_ao   [B_ * MQ * C_];

// Device-side pointer selection — NEVER pass __device__ symbols from host code
// (on GB300, host-shadow addresses are ATS-dereferenceable and fail silently).
__device__ __forceinline__ const float* in_ptr(int id) {
    switch (id) { case 0: return g_tq; case 1: return g_tloc; default: return g_tmg; }
}
__device__ __forceinline__ float* out_ptr(int id) {
    switch (id) { case 0: return g_q; case 1: return g_kvloc; default: return g_kvmg; }
}

// ---------------- packed f32x2 primitives ----------------
__device__ __forceinline__ u64 pack2(float a, float b) {
    u64 r; asm("mov.b64 %0, {%1, %2};" : "=l"(r) : "f"(a), "f"(b)); return r;
}
__device__ __forceinline__ void unpack2(u64 v, float& a, float& b) {
    asm("mov.b64 {%0, %1}, %2;" : "=f"(a), "=f"(b) : "l"(v));
}
__device__ __forceinline__ u64 ffma2(u64 a, u64 b, u64 c) {
    u64 d; asm("fma.rn.f32x2 %0, %1, %2, %3;" : "=l"(d) : "l"(a), "l"(b), "l"(c)); return d;
}

// ---------------- 1) query tokens: gather + LayerNorm ----------------
__global__ void build_tq(const float* __restrict__ feat,
                         const float* __restrict__ lnw, const float* __restrict__ lnb) {
    int warp = threadIdx.x / 32, lane = threadIdx.x % 32;
    int qg = blockIdx.x * 8 + warp;
    int b = qg / MQ;
    int q = qg % MQ;
    int w = q / 16, t = q % 16;
    int wy = w / 16, wx = w % 16;
    float vals[8];
    float sum = 0.f;
#pragma unroll
    for (int i = 0; i < 8; i++) {
        int c  = lane + i * 32;
        int ch = t * 16 + c / 16;
        int iy = (c / 4) % 4;
        int ix = c % 4;
        int y  = wy * 4 + iy, x = wx * 4 + ix;
        float v = feat[(((size_t)b * 256 + ch) * 64 + y) * 64 + x];
        vals[i] = v; sum += v;
    }
#pragma unroll
    for (int o = 16; o; o >>= 1) sum += __shfl_xor_sync(0xffffffffu, sum, o);
    float mu = sum * (1.f / 256.f);
    float vs = 0.f;
#pragma unroll
    for (int i = 0; i < 8; i++) { float d = vals[i] - mu; vs += d * d; }
#pragma unroll
    for (int o = 16; o; o >>= 1) vs += __shfl_xor_sync(0xffffffffu, vs, o);
    float rstd = rsqrtf(vs * (1.f / 256.f) + 1e-5f);
#pragma unroll
    for (int i = 0; i < 8; i++) {
        int c = lane + i * 32;
        g_tq[(size_t)qg * 256 + c] = (vals[i] - mu) * rstd * lnw[c] + lnb[c];
    }
}

// ---------------- 2) local tokens: gather (zero-padded) ----------------
__global__ void build_tloc(const float* __restrict__ feat) {
    int idx = blockIdx.x * 256 + threadIdx.x;
    int c   = idx % 256;
    int row = idx / 256;
    int b   = row / MLOC;
    int wt  = row % MLOC;
    int w   = wt / 64, t = wt % 64;
    int ch  = t * 4 + c / 64;
    int iy  = (c / 8) % 8;
    int ix  = c % 8;
    int y   = (w / 16) * 4 + iy - 2;
    int x   = (w % 16) * 4 + ix - 2;
    float v = 0.f;
    if ((unsigned)y < 64u && (unsigned)x < 64u)
        v = feat[(((size_t)b * 256 + ch) * 64 + y) * 64 + x];
    g_tloc[idx] = v;
}

// ---------------- 3) mid/glb pooled tokens ----------------
__global__ void build_tmg(const float* __restrict__ feat) {
    int l = blockIdx.x, b = blockIdx.y, c = threadIdx.x;
    const float* f = feat + ((size_t)b * 256 + c) * 4096;
    float v;
    if (l < 1024) {
        int y = l / 32, x = l % 32;
        v = 0.25f * (f[(2 * y) * 64 + 2 * x]     + f[(2 * y) * 64 + 2 * x + 1] +
                     f[(2 * y + 1) * 64 + 2 * x] + f[(2 * y + 1) * 64 + 2 * x + 1]);
    } else {
        int g = l - 1024;
        int y = g / 16, x = g % 16;
        float s = 0.f;
#pragma unroll
        for (int dy = 0; dy < 4; dy++)
#pragma unroll
            for (int dx = 0; dx < 4; dx++) s += f[(4 * y + dy) * 64 + 4 * x + dx];
        v = 0.0625f * s;
    }
    g_tmg[((size_t)b * MG + l) * 256 + c] = v;
}

// ---------------- 4) unified projection GEMM (all three projections, one launch) ----------------
// C[m][n] = sum_k A[m][k]*qkv_w[k][wcol0+n] + qkv_b[wcol0+n]
__global__ void __launch_bounds__(256) gemm_all(
    const float* __restrict__ Wm, const float* __restrict__ bias)
{
    int id = blockIdx.x;
    int sel, Mrows, wcol0, ldc, nn;
    if (id < 1024)      { sel = 1; Mrows = MLOC; wcol0 = 256; ldc = 512; nn = 4; }            // loc KV (big, first)
    else if (id < 1152) { sel = 0; id -= 1024; Mrows = MQ;  wcol0 = 0;   ldc = 256; nn = 2; } // Q
    else                { sel = 2; id -= 1152; Mrows = MG;  wcol0 = 256; ldc = 512; nn = 4; } // mg KV
    int per_b = (Mrows / 128) * nn;
    int b  = id / per_b;
    int r  = id % per_b;
    int mt = r / nn, nt = r % nn;
    const int m0 = mt * 128, n0 = nt * 128;
    const float* Ab = in_ptr(sel) + (size_t)b * Mrows * 256;
    float* Cb = out_ptr(sel) + (size_t)b * Mrows * ldc;

    __shared__ u64   As2[16][132];  // A duplicated into (a,a) pairs
    __shared__ float Bs [16][132];
    const int tid = threadIdx.x;
    const int tx = tid & 15, ty = tid >> 4;
    u64 acc2[8][4];
#pragma unroll
    for (int i = 0; i < 8; i++)
#pragma unroll
        for (int j = 0; j < 4; j++) acc2[i][j] = 0ull;

    for (int k0 = 0; k0 < 256; k0 += 16) {
#pragma unroll
        for (int j = 0; j < 2; j++) {
            int idx = tid + j * 256;
            int m = idx >> 2, kq = idx & 3;
            float4 v = *(const float4*)(Ab + (size_t)(m0 + m) * 256 + k0 + kq * 4);
            As2[kq * 4 + 0][m] = pack2(v.x, v.x);
            As2[kq * 4 + 1][m] = pack2(v.y, v.y);
            As2[kq * 4 + 2][m] = pack2(v.z, v.z);
            As2[kq * 4 + 3][m] = pack2(v.w, v.w);
        }
#pragma unroll
        for (int j = 0; j < 2; j++) {
            int idx = tid + j * 256;
            int kk = idx >> 5, nq = idx & 31;
            *(float4*)&Bs[kk][nq * 4] =
                *(const float4*)(Wm + (size_t)(k0 + kk) * 768 + wcol0 + n0 + nq * 4);
        }
        __syncthreads();
#pragma unroll
        for (int k = 0; k < 16; k++) {
            u64 b2[4];
#pragma unroll
            for (int jp = 0; jp < 4; jp++)
                b2[jp] = *(const u64*)&Bs[k][2 * tx + 32 * jp];
#pragma unroll
            for (int i = 0; i < 8; i++) {
                u64 a2 = As2[k][ty * 8 + i];
#pragma unroll
                for (int jp = 0; jp < 4; jp++)
                    acc2[i][jp] = ffma2(a2, b2[jp], acc2[i][jp]);
            }
        }
        __syncthreads();
    }
#pragma unroll
    for (int i = 0; i < 8; i++) {
        int m = m0 + ty * 8 + i;
#pragma unroll
        for (int jp = 0; jp < 4; jp++) {
            int n = n0 + 2 * tx + 32 * jp;
            float c0, c1; unpack2(acc2[i][jp], c0, c1);
            float2 bv = *(const float2*)&bias[wcol0 + n];
            *(float2*)&Cb[(size_t)m * ldc + n] = make_float2(c0 + bv.x, c1 + bv.y);
        }
    }
}

// ---------------- 5) attention: 2 windows/block, cp.async double-buffered staging ----------------
#define NCHUNK 176   // 16 local chunks (4 keys x 2 windows) + 160 shared chunks (8 keys)
__global__ void __launch_bounds__(256) attn_kernel() {
    const int tid   = threadIdx.x;
    const int b     = blockIdx.y;
    const int wpair = blockIdx.x;
    const int wloc  = tid >> 7;              // which of the 2 windows
    const int w     = wpair * 2 + wloc;
    const int head  = (tid >> 4) & 7;
    const int qi    = tid & 15;

    __shared__ float skv[2][8 * 512];        // 2 x 16 KB ping-pong

    const float4* qp = (const float4*)(g_q + ((size_t)(b * MQ + w * 16 + qi) * 256 + head * 32));
    const float scale = 0.17677669529663687f;   // 1/sqrt(32)
    u64 q2[16];
#pragma unroll
    for (int j = 0; j < 8; j++) {
        float4 q = qp[j];
        q2[2 * j]     = pack2(q.x * scale, q.y * scale);
        q2[2 * j + 1] = pack2(q.z * scale, q.w * scale);
    }
    float l = 0.f;
    u64 acc2[16];
#pragma unroll
    for (int j = 0; j < 16; j++) acc2[j] = 0ull;

    const float4* kvloc4 = (const float4*)g_kvloc + (size_t)(b * MLOC + wpair * 128) * 128;
    const float4* kvmg4  = (const float4*)g_kvmg + (size_t)b * MG * 128;
    uint32_t sbase[2] = { (uint32_t)__cvta_generic_to_shared(&skv[0][0]),
                          (uint32_t)__cvta_generic_to_shared(&skv[1][0]) };

#define ISSUE(ch, buf) do {                                                             \
        uint32_t sb_ = sbase[buf];                                                      \
        if ((ch) < 16) {                                                                \
            _Pragma("unroll")                                                           \
            for (int j_ = 0; j_ < 4; j_++) {                                            \
                int idx_ = tid + j_ * 256;                                              \
                int r_ = idx_ >> 7;                                                     \
                int row_ = ((r_ >> 2) << 6) + (ch) * 4 + (r_ & 3);                      \
                const float4* src_ = kvloc4 + (size_t)row_ * 128 + (idx_ & 127);        \
                asm volatile("cp.async.cg.shared.global [%0], [%1], 16;"                \
                             :: "r"(sb_ + idx_ * 16), "l"(src_));                       \
            }                                                                           \
        } else {                                                                        \
            const float4* src0_ = kvmg4 + (size_t)((ch) - 16) * 1024;                   \
            _Pragma("unroll")                                                           \
            for (int j_ = 0; j_ < 4; j_++) {                                            \
                int idx_ = tid + j_ * 256;                                              \
                asm volatile("cp.async.cg.shared.global [%0], [%1], 16;"                \
                             :: "r"(sb_ + idx_ * 16), "l"(src0_ + idx_));               \
            }                                                                           \
        }                                                                               \
        asm volatile("cp.async.commit_group;");                                        \
    } while (0)

    ISSUE(0, 0);
    for (int ch = 0; ch < NCHUNK; ch++) {
        if (ch + 1 < NCHUNK) {
            ISSUE(ch + 1, (ch + 1) & 1);
            asm volatile("cp.async.wait_group 1;" ::: "memory");
        } else {
            asm volatile("cp.async.wait_group 0;" ::: "memory");
        }
        __syncthreads();
        const float* base = &skv[ch & 1][0];
        int kbeg = (ch < 16) ? wloc * 4 : 0;
        int kend = (ch < 16) ? kbeg + 4 : 8;
#pragma unroll 4
        for (int kk = kbeg; kk < kend; kk++) {
            const ulonglong2* krow = (const ulonglong2*)(base + kk * 512 + head * 32);
            u64 sa = 0ull, sb = 0ull, sc = 0ull, sd = 0ull;
#pragma unroll
            for (int j = 0; j < 4; j++) {
                ulonglong2 k0 = krow[2 * j];
                ulonglong2 k1 = krow[2 * j + 1];
                sa = ffma2(q2[4 * j],     k0.x, sa);
                sb = ffma2(q2[4 * j + 1], k0.y, sb);
                sc = ffma2(q2[4 * j + 2], k1.x, sc);
                sd = ffma2(q2[4 * j + 3], k1.y, sd);
            }
            float a0, a1, b0, b1, c0, c1, d0, d1;
            unpack2(sa, a0, a1); unpack2(sb, b0, b1);
            unpack2(sc, c0, c1); unpack2(sd, d0, d1);
            float s = ((a0 + a1) + (b0 + b1)) + ((c0 + c1) + (d0 + d1));
            float wgt = __expf(s);
            l += wgt;
            u64 w2 = pack2(wgt, wgt);
            const ulonglong2* vrow = (const ulonglong2*)(base + kk * 512 + 256 + head * 32);
#pragma unroll
            for (int j = 0; j < 8; j++) {
                ulonglong2 v = vrow[j];
                acc2[2 * j]     = ffma2(w2, v.x, acc2[2 * j]);
                acc2[2 * j + 1] = ffma2(w2, v.y, acc2[2 * j + 1]);
            }
        }
        __syncthreads();
    }

    float inv = 1.0f / l;
    float4* op = (float4*)(g_ao + ((size_t)(b * MQ + w * 16 + qi) * 256 + head * 32));
#pragma unroll
    for (int j = 0; j < 8; j++) {
        float x0, x1, x2, x3;
        unpack2(acc2[2 * j], x0, x1);
        unpack2(acc2[2 * j + 1], x2, x3);
        op[j] = make_float4(x0 * inv, x1 * inv, x2 * inv, x3 * inv);
    }
}

// ---------------- 6) output projection + scatter + residual ----------------
__global__ void __launch_bounds__(256) gemm_out(
    const float* __restrict__ feat, float* __restrict__ out,
    const float* __restrict__ Wm, const float* __restrict__ bias)
{
    const int m0 = blockIdx.x * 128, n0 = blockIdx.y * 128, b = blockIdx.z;
    const float* Ab = g_ao + (size_t)b * MQ * 256;
    __shared__ u64   As2[16][132];
    __shared__ float Bs [16][132];
    const int tid = threadIdx.x;
    const int tx = tid & 15, ty = tid >> 4;
    u64 acc2[8][4];
#pragma unroll
    for (int i = 0; i < 8; i++)
#pragma unroll
        for (int j = 0; j < 4; j++) acc2[i][j] = 0ull;

    for (int k0 = 0; k0 < 256; k0 += 16) {
#pragma unroll
        for (int j = 0; j < 2; j++) {
            int idx = tid + j * 256;
            int m = idx >> 2, kq = idx & 3;
            float4 v = *(const float4*)(Ab + (size_t)(m0 + m) * 256 + k0 + kq * 4);
            As2[kq * 4 + 0][m] = pack2(v.x, v.x);
            As2[kq * 4 + 1][m] = pack2(v.y, v.y);
            As2[kq * 4 + 2][m] = pack2(v.z, v.z);
            As2[kq * 4 + 3][m] = pack2(v.w, v.w);
        }
#pragma unroll
        for (int j = 0; j < 2; j++) {
            int idx = tid + j * 256;
            int kk = idx >> 5, nq = idx & 31;
            *(float4*)&Bs[kk][nq * 4] =
                *(const float4*)(Wm + (size_t)(k0 + kk) * 256 + n0 + nq * 4);
        }
        __syncthreads();
#pragma unroll
        for (int k = 0; k < 16; k++) {
            u64 b2[4];
#pragma unroll
            for (int jp = 0; jp < 4; jp++)
                b2[jp] = *(const u64*)&Bs[k][2 * tx + 32 * jp];
#pragma unroll
            for (int i = 0; i < 8; i++) {
                u64 a2 = As2[k][ty * 8 + i];
#pragma unroll
                for (int jp = 0; jp < 4; jp++)
                    acc2[i][jp] = ffma2(a2, b2[jp], acc2[i][jp]);
            }
        }
        __syncthreads();
    }
#pragma unroll
    for (int i = 0; i < 8; i++) {
        int q = m0 + ty * 8 + i;
        int w = q / 16, t = q % 16;
        int y = (w / 16) * 4 + t / 4;
        int x = (w % 16) * 4 + t % 4;
        int pix = y * 64 + x;
#pragma unroll
        for (int jp = 0; jp < 4; jp++) {
            int n = n0 + 2 * tx + 32 * jp;
            float c0, c1; unpack2(acc2[i][jp], c0, c1);
            size_t o0 = (((size_t)b * 256 + n) << 12) + pix;
            size_t o1 = o0 + 4096;
            out[o0] = c0 + bias[n] + feat[o0];
            out[o1] = c1 + bias[n + 1] + feat[o1];
        }
    }
}

// ---------------- launch (only harness pointers cross host->device) ----------------
extern "C" void kernel_launch(void* const* d_in, const int* in_sizes, int n_in,
                              void* d_out, int out_size) {
    const float* feat  = (const float*)d_in[0];
    const float* qkv_w = (const float*)d_in[1];
    const float* qkv_b = (const float*)d_in[2];
    const float* out_w = (const float*)d_in[3];
    const float* out_b = (const float*)d_in[4];
    const float* ln_w  = (const float*)d_in[5];
    const float* ln_b  = (const float*)d_in[6];
    float* out = (float*)d_out;

    build_tq  <<<(B_ * MQ) / 8, 256>>>(feat, ln_w, ln_b);
    build_tloc<<<(int)(((size_t)B_ * MLOC * 256) / 256), 256>>>(feat);
    build_tmg <<<dim3(MG, B_), 256>>>(feat);

    // all three projections in one launch: 1024 (loc) + 128 (Q) + 80 (mg) blocks
    gemm_all<<<1232, 256>>>(qkv_w, qkv_b);

    attn_kernel<<<dim3(NW / 2, B_), 256>>>();

    gemm_out<<<dim3(MQ / 128, 256 / 128, B_), 256>>>(feat, out, out_w, out_b);
}

// round 12
// speedup vs baseline: 1.6372x; 1.6372x over previous
#include <cuda_runtime.h>
#include <cstdint>

#define B_   2
#define C_   256
#define MLOC 16384   // NW*64 local tokens per batch
#define MQ   4096    // NW*16 query tokens per batch
#define MG   1280    // 1024 mid + 256 glb tokens per batch
#define NW   256
#define LK   1344

typedef unsigned long long u64;

// ---------------- scratch (device globals; ONLY referenced from device code) ----------------
__device__ float g_tq   [B_ * MQ * C_];
__device__ float g_tloc [(size_t)B_ * MLOC * C_];
__device__ float g_tmg  [B_ * MG * C_];
__device__ float g_q    [B_ * MQ * C_];
__device__ float g_kvloc[(size_t)B_ * MLOC * 512];  // K+bias:0..255, V+bias:256..511
__device__ float g_kvmg [B_ * MG * 512];
__device__ float g_ao   [B_ * MQ * C_];

// Device-side pointer selection — NEVER pass __device__ symbols from host code
// (on GB300, host-shadow addresses are ATS-dereferenceable and fail silently).
__device__ __forceinline__ const float* in_ptr(int id) {
    switch (id) { case 0: return g_tq; case 1: return g_tloc; default: return g_tmg; }
}
__device__ __forceinline__ float* out_ptr(int id) {
    switch (id) { case 0: return g_q; case 1: return g_kvloc; default: return g_kvmg; }
}

// ---------------- packed f32x2 primitives ----------------
__device__ __forceinline__ u64 pack2(float a, float b) {
    u64 r; asm("mov.b64 %0, {%1, %2};" : "=l"(r) : "f"(a), "f"(b)); return r;
}
__device__ __forceinline__ void unpack2(u64 v, float& a, float& b) {
    asm("mov.b64 {%0, %1}, %2;" : "=f"(a), "=f"(b) : "l"(v));
}
__device__ __forceinline__ u64 ffma2(u64 a, u64 b, u64 c) {
    u64 d; asm("fma.rn.f32x2 %0, %1, %2, %3;" : "=l"(d) : "l"(a), "l"(b), "l"(c)); return d;
}

// ---------------- 1) query tokens: gather + LayerNorm ----------------
__global__ void build_tq(const float* __restrict__ feat,
                         const float* __restrict__ lnw, const float* __restrict__ lnb) {
    int warp = threadIdx.x / 32, lane = threadIdx.x % 32;
    int qg = blockIdx.x * 8 + warp;
    int b = qg / MQ;
    int q = qg % MQ;
    int w = q / 16, t = q % 16;
    int wy = w / 16, wx = w % 16;
    float vals[8];
    float sum = 0.f;
#pragma unroll
    for (int i = 0; i < 8; i++) {
        int c  = lane + i * 32;
        int ch = t * 16 + c / 16;
        int iy = (c / 4) % 4;
        int ix = c % 4;
        int y  = wy * 4 + iy, x = wx * 4 + ix;
        float v = feat[(((size_t)b * 256 + ch) * 64 + y) * 64 + x];
        vals[i] = v; sum += v;
    }
#pragma unroll
    for (int o = 16; o; o >>= 1) sum += __shfl_xor_sync(0xffffffffu, sum, o);
    float mu = sum * (1.f / 256.f);
    float vs = 0.f;
#pragma unroll
    for (int i = 0; i < 8; i++) { float d = vals[i] - mu; vs += d * d; }
#pragma unroll
    for (int o = 16; o; o >>= 1) vs += __shfl_xor_sync(0xffffffffu, vs, o);
    float rstd = rsqrtf(vs * (1.f / 256.f) + 1e-5f);
#pragma unroll
    for (int i = 0; i < 8; i++) {
        int c = lane + i * 32;
        g_tq[(size_t)qg * 256 + c] = (vals[i] - mu) * rstd * lnw[c] + lnb[c];
    }
}

// ---------------- 2) local tokens: gather (zero-padded) ----------------
__global__ void build_tloc(const float* __restrict__ feat) {
    int idx = blockIdx.x * 256 + threadIdx.x;
    int c   = idx % 256;
    int row = idx / 256;
    int b   = row / MLOC;
    int wt  = row % MLOC;
    int w   = wt / 64, t = wt % 64;
    int ch  = t * 4 + c / 64;
    int iy  = (c / 8) % 8;
    int ix  = c % 8;
    int y   = (w / 16) * 4 + iy - 2;
    int x   = (w % 16) * 4 + ix - 2;
    float v = 0.f;
    if ((unsigned)y < 64u && (unsigned)x < 64u)
        v = feat[(((size_t)b * 256 + ch) * 64 + y) * 64 + x];
    g_tloc[idx] = v;
}

// ---------------- 3) mid/glb pooled tokens ----------------
__global__ void build_tmg(const float* __restrict__ feat) {
    int l = blockIdx.x, b = blockIdx.y, c = threadIdx.x;
    const float* f = feat + ((size_t)b * 256 + c) * 4096;
    float v;
    if (l < 1024) {
        int y = l / 32, x = l % 32;
        v = 0.25f * (f[(2 * y) * 64 + 2 * x]     + f[(2 * y) * 64 + 2 * x + 1] +
                     f[(2 * y + 1) * 64 + 2 * x] + f[(2 * y + 1) * 64 + 2 * x + 1]);
    } else {
        int g = l - 1024;
        int y = g / 16, x = g % 16;
        float s = 0.f;
#pragma unroll
        for (int dy = 0; dy < 4; dy++)
#pragma unroll
            for (int dx = 0; dx < 4; dx++) s += f[(4 * y + dy) * 64 + 4 * x + dx];
        v = 0.0625f * s;
    }
    g_tmg[((size_t)b * MG + l) * 256 + c] = v;
}

// ---------------- 4) unified projection GEMM (R10-proven core, merged launch) ----------------
__global__ void __launch_bounds__(256) gemm_all(
    const float* __restrict__ Wm, const float* __restrict__ bias)
{
    int id = blockIdx.x;
    int sel, Mrows, wcol0, ldc, nn;
    if (id < 1024)      { sel = 1; Mrows = MLOC; wcol0 = 256; ldc = 512; nn = 4; }            // loc KV
    else if (id < 1152) { sel = 0; id -= 1024; Mrows = MQ;  wcol0 = 0;   ldc = 256; nn = 2; } // Q
    else                { sel = 2; id -= 1152; Mrows = MG;  wcol0 = 256; ldc = 512; nn = 4; } // mg KV
    int per_b = (Mrows / 128) * nn;
    int b  = id / per_b;
    int r  = id % per_b;
    int mt = r / nn, nt = r % nn;
    const int m0 = mt * 128, n0 = nt * 128;
    const float* Ab = in_ptr(sel) + (size_t)b * Mrows * 256;
    float* Cb = out_ptr(sel) + (size_t)b * Mrows * ldc;

    __shared__ float As[16][129];   // [k][m]
    __shared__ float Bs[16][128];   // [k][n]
    const int tid = threadIdx.x;
    const int tx = tid & 15, ty = tid >> 4;
    u64 acc2[8][4];
#pragma unroll
    for (int i = 0; i < 8; i++)
#pragma unroll
        for (int j = 0; j < 4; j++) acc2[i][j] = 0ull;

    for (int k0 = 0; k0 < 256; k0 += 16) {
#pragma unroll
        for (int i = 0; i < 8; i++) {
            int flat = tid + i * 256;
            int mm = flat >> 4, kk = flat & 15;
            As[kk][mm] = Ab[(size_t)(m0 + mm) * 256 + k0 + kk];
        }
#pragma unroll
        for (int i = 0; i < 8; i++) {
            int flat = tid + i * 256;
            int kk = flat >> 7, nnq = flat & 127;
            Bs[kk][nnq] = Wm[(size_t)(k0 + kk) * 768 + wcol0 + n0 + nnq];
        }
        __syncthreads();
#pragma unroll
        for (int k = 0; k < 16; k++) {
            u64 b2[4];
#pragma unroll
            for (int jp = 0; jp < 4; jp++)
                b2[jp] = *(const u64*)&Bs[k][2 * tx + 32 * jp];
#pragma unroll
            for (int i = 0; i < 8; i++) {
                float a = As[k][ty * 8 + i];
                u64 a2 = pack2(a, a);
#pragma unroll
                for (int jp = 0; jp < 4; jp++)
                    acc2[i][jp] = ffma2(a2, b2[jp], acc2[i][jp]);
            }
        }
        __syncthreads();
    }
#pragma unroll
    for (int i = 0; i < 8; i++) {
        int m = m0 + ty * 8 + i;
#pragma unroll
        for (int jp = 0; jp < 4; jp++) {
            int n = n0 + 2 * tx + 32 * jp;
            float c0, c1; unpack2(acc2[i][jp], c0, c1);
            float2 bv = *(const float2*)&bias[wcol0 + n];
            *(float2*)&Cb[(size_t)m * ldc + n] = make_float2(c0 + bv.x, c1 + bv.y);
        }
    }
}

// ---------------- 5) attention: per-head blocks, head-sliced K/V staging ----------------
// grid (qtile=32, head=8, b=2); 128 threads, thread = one query token, d=32 dims of `head`
// chunks: 8 local (8 win x 8 keys) + 40 global (32 keys); each key = 64 floats (K32|V32)
#define NCH 48
__global__ void __launch_bounds__(128) attn_kernel() {
    const int tid   = threadIdx.x;
    const int qtile = blockIdx.x;
    const int head  = blockIdx.y;
    const int b     = blockIdx.z;
    const int wbase = qtile * 8;
    const int win   = tid >> 4;             // this thread's window within the 8
    const int q     = qtile * 128 + tid;    // query token in batch

    __shared__ __align__(16) float sbuf[2][4096];   // 2 x 16 KB ping-pong

    const float4* qp = (const float4*)(g_q + ((size_t)(b * MQ + q) * 256 + head * 32));
    const float scale = 0.17677669529663687f;   // 1/sqrt(32)
    u64 q2[16];
#pragma unroll
    for (int j = 0; j < 8; j++) {
        float4 qv = qp[j];
        q2[2 * j]     = pack2(qv.x * scale, qv.y * scale);
        q2[2 * j + 1] = pack2(qv.z * scale, qv.w * scale);
    }
    float l = 0.f;
    u64 acc2[16];
#pragma unroll
    for (int j = 0; j < 16; j++) acc2[j] = 0ull;

    const float4* kvloc4 = (const float4*)g_kvloc;
    const float4* kvmg4  = (const float4*)g_kvmg;
    const int head8 = head * 8;
    const int bML = b * MLOC, bMG = b * MG;
    uint32_t sbase[2] = { (uint32_t)__cvta_generic_to_shared(&sbuf[0][0]),
                          (uint32_t)__cvta_generic_to_shared(&sbuf[1][0]) };

#define ISSUE(ch, buf) do {                                                              \
        uint32_t sb_ = sbase[buf];                                                       \
        if ((ch) < 8) {                                                                  \
            _Pragma("unroll")                                                            \
            for (int j_ = 0; j_ < 8; j_++) {                                             \
                int idx_ = tid + j_ * 128;                                               \
                int slot_ = idx_ >> 4, j4_ = idx_ & 15;                                  \
                int grow_ = (wbase + (slot_ >> 3)) * 64 + (ch) * 8 + (slot_ & 7);        \
                int col_ = (j4_ < 8) ? head8 + j4_ : 64 + head8 + (j4_ - 8);             \
                asm volatile("cp.async.cg.shared.global [%0], [%1], 16;"                 \
                    :: "r"(sb_ + idx_ * 16),                                             \
                       "l"(kvloc4 + (size_t)(bML + grow_) * 128 + col_));                \
            }                                                                            \
        } else {                                                                         \
            _Pragma("unroll")                                                            \
            for (int j_ = 0; j_ < 4; j_++) {                                             \
                int idx_ = tid + j_ * 128;                                               \
                int key_ = idx_ >> 4, j4_ = idx_ & 15;                                   \
                int grow_ = bMG + ((ch) - 8) * 32 + key_;                                \
                int col_ = (j4_ < 8) ? head8 + j4_ : 64 + head8 + (j4_ - 8);             \
                asm volatile("cp.async.cg.shared.global [%0], [%1], 16;"                 \
                    :: "r"(sb_ + idx_ * 16),                                             \
                       "l"(kvmg4 + (size_t)grow_ * 128 + col_));                         \
            }                                                                            \
        }                                                                                \
        asm volatile("cp.async.commit_group;");                                         \
    } while (0)

    ISSUE(0, 0);
    for (int ch = 0; ch < NCH; ch++) {
        if (ch + 1 < NCH) {
            ISSUE(ch + 1, (ch + 1) & 1);
            asm volatile("cp.async.wait_group 1;" ::: "memory");
        } else {
            asm volatile("cp.async.wait_group 0;" ::: "memory");
        }
        __syncthreads();
        const float* base = &sbuf[ch & 1][0];
        const float* kptr0;
        int nk;
        if (ch < 8) { kptr0 = base + (win * 8) * 64; nk = 8; }
        else        { kptr0 = base;                  nk = 32; }
#pragma unroll 8
        for (int kk = 0; kk < nk; kk++) {
            const float* kp = kptr0 + kk * 64;
            const ulonglong2* krow = (const ulonglong2*)kp;
            u64 sa = 0ull, sb2 = 0ull, sc = 0ull, sd = 0ull;
#pragma unroll
            for (int j = 0; j < 4; j++) {
                ulonglong2 k0 = krow[2 * j];
                ulonglong2 k1 = krow[2 * j + 1];
                sa  = ffma2(q2[4 * j],     k0.x, sa);
                sb2 = ffma2(q2[4 * j + 1], k0.y, sb2);
                sc  = ffma2(q2[4 * j + 2], k1.x, sc);
                sd  = ffma2(q2[4 * j + 3], k1.y, sd);
            }
            float a0, a1, b0, b1, c0, c1, d0, d1;
            unpack2(sa, a0, a1); unpack2(sb2, b0, b1);
            unpack2(sc, c0, c1); unpack2(sd, d0, d1);
            float s = ((a0 + a1) + (b0 + b1)) + ((c0 + c1) + (d0 + d1));
            float wgt = __expf(s);
            l += wgt;
            u64 w2 = pack2(wgt, wgt);
            const ulonglong2* vrow = (const ulonglong2*)(kp + 32);
#pragma unroll
            for (int j = 0; j < 8; j++) {
                ulonglong2 v = vrow[j];
                acc2[2 * j]     = ffma2(w2, v.x, acc2[2 * j]);
                acc2[2 * j + 1] = ffma2(w2, v.y, acc2[2 * j + 1]);
            }
        }
        __syncthreads();
    }

    float inv = 1.0f / l;
    float4* op = (float4*)(g_ao + ((size_t)(b * MQ + q) * 256 + head * 32));
#pragma unroll
    for (int j = 0; j < 8; j++) {
        float x0, x1, x2, x3;
        unpack2(acc2[2 * j], x0, x1);
        unpack2(acc2[2 * j + 1], x2, x3);
        op[j] = make_float4(x0 * inv, x1 * inv, x2 * inv, x3 * inv);
    }
}

// ---------------- 6) output projection + scatter + residual (R10-proven) ----------------
__global__ void __launch_bounds__(256) gemm_out(
    const float* __restrict__ feat, float* __restrict__ out,
    const float* __restrict__ Wm, const float* __restrict__ bias)
{
    const int m0 = blockIdx.x * 128, n0 = blockIdx.y * 128, b = blockIdx.z;
    const float* Ab = g_ao + (size_t)b * MQ * 256;
    __shared__ float As[16][129];
    __shared__ float Bs[16][128];
    const int tid = threadIdx.x;
    const int tx = tid & 15, ty = tid >> 4;
    u64 acc2[8][4];
#pragma unroll
    for (int i = 0; i < 8; i++)
#pragma unroll
        for (int j = 0; j < 4; j++) acc2[i][j] = 0ull;

    for (int k0 = 0; k0 < 256; k0 += 16) {
#pragma unroll
        for (int i = 0; i < 8; i++) {
            int flat = tid + i * 256;
            int mm = flat >> 4, kk = flat & 15;
            As[kk][mm] = Ab[(size_t)(m0 + mm) * 256 + k0 + kk];
        }
#pragma unroll
        for (int i = 0; i < 8; i++) {
            int flat = tid + i * 256;
            int kk = flat >> 7, nnq = flat & 127;
            Bs[kk][nnq] = Wm[(size_t)(k0 + kk) * 256 + n0 + nnq];
        }
        __syncthreads();
#pragma unroll
        for (int k = 0; k < 16; k++) {
            u64 b2[4];
#pragma unroll
            for (int jp = 0; jp < 4; jp++)
                b2[jp] = *(const u64*)&Bs[k][2 * tx + 32 * jp];
#pragma unroll
            for (int i = 0; i < 8; i++) {
                float a = As[k][ty * 8 + i];
                u64 a2 = pack2(a, a);
#pragma unroll
                for (int jp = 0; jp < 4; jp++)
                    acc2[i][jp] = ffma2(a2, b2[jp], acc2[i][jp]);
            }
        }
        __syncthreads();
    }
#pragma unroll
    for (int i = 0; i < 8; i++) {
        int q = m0 + ty * 8 + i;
        int w = q / 16, t = q % 16;
        int y = (w / 16) * 4 + t / 4;
        int x = (w % 16) * 4 + t % 4;
        int pix = y * 64 + x;
#pragma unroll
        for (int jp = 0; jp < 4; jp++) {
            int n = n0 + 2 * tx + 32 * jp;
            float c0, c1; unpack2(acc2[i][jp], c0, c1);
            size_t o0 = (((size_t)b * 256 + n) << 12) + pix;
            size_t o1 = o0 + 4096;
            out[o0] = c0 + bias[n] + feat[o0];
            out[o1] = c1 + bias[n + 1] + feat[o1];
        }
    }
}

// ---------------- launch (only harness pointers cross host->device) ----------------
extern "C" void kernel_launch(void* const* d_in, const int* in_sizes, int n_in,
                              void* d_out, int out_size) {
    const float* feat  = (const float*)d_in[0];
    const float* qkv_w = (const float*)d_in[1];
    const float* qkv_b = (const float*)d_in[2];
    const float* out_w = (const float*)d_in[3];
    const float* out_b = (const float*)d_in[4];
    const float* ln_w  = (const float*)d_in[5];
    const float* ln_b  = (const float*)d_in[6];
    float* out = (float*)d_out;

    build_tq  <<<(B_ * MQ) / 8, 256>>>(feat, ln_w, ln_b);
    build_tloc<<<(int)(((size_t)B_ * MLOC * 256) / 256), 256>>>(feat);
    build_tmg <<<dim3(MG, B_), 256>>>(feat);

    gemm_all<<<1232, 256>>>(qkv_w, qkv_b);

    attn_kernel<<<dim3(32, 8, B_), 128>>>();

    gemm_out<<<dim3(MQ / 128, 256 / 128, B_), 256>>>(feat, out, out_w, out_b);
}

// round 13
// speedup vs baseline: 1.7643x; 1.0776x over previous
#include <cuda_runtime.h>
#include <cstdint>

#define B_   2
#define C_   256
#define MLOC 16384   // NW*64 local tokens per batch
#define MQ   4096    // NW*16 query tokens per batch
#define MG   1280    // 1024 mid + 256 glb tokens per batch
#define NW   256
#define LK   1344

typedef unsigned long long u64;

// ---------------- scratch (device globals; ONLY referenced from device code) ----------------
__device__ float g_tq   [B_ * MQ * C_];
__device__ float g_tloc [(size_t)B_ * MLOC * C_];
__device__ float g_tmg  [B_ * MG * C_];
__device__ float g_q    [B_ * MQ * C_];
__device__ float g_kvloc[(size_t)B_ * MLOC * 512];  // K+bias:0..255, V+bias:256..511
__device__ float g_kvmg [B_ * MG * 512];
__device__ float g_ao   [B_ * MQ * C_];

// Device-side pointer selection — NEVER pass __device__ symbols from host code
// (on GB300, host-shadow addresses are ATS-dereferenceable and fail silently).
__device__ __forceinline__ const float* in_ptr(int id) {
    switch (id) { case 0: return g_tq; case 1: return g_tloc; default: return g_tmg; }
}
__device__ __forceinline__ float* out_ptr(int id) {
    switch (id) { case 0: return g_q; case 1: return g_kvloc; default: return g_kvmg; }
}

// ---------------- packed f32x2 primitives ----------------
__device__ __forceinline__ u64 pack2(float a, float b) {
    u64 r; asm("mov.b64 %0, {%1, %2};" : "=l"(r) : "f"(a), "f"(b)); return r;
}
__device__ __forceinline__ void unpack2(u64 v, float& a, float& b) {
    asm("mov.b64 {%0, %1}, %2;" : "=f"(a), "=f"(b) : "l"(v));
}
__device__ __forceinline__ u64 ffma2(u64 a, u64 b, u64 c) {
    u64 d; asm("fma.rn.f32x2 %0, %1, %2, %3;" : "=l"(d) : "l"(a), "l"(b), "l"(c)); return d;
}
__device__ __forceinline__ u64 add2(u64 a, u64 b) {
    u64 d; asm("add.rn.f32x2 %0, %1, %2;" : "=l"(d) : "l"(a), "l"(b)); return d;
}
__device__ __forceinline__ float ex2(float x) {
    float r; asm("ex2.approx.f32 %0, %1;" : "=f"(r) : "f"(x)); return r;
}

// ---------------- 1) query tokens: gather + LayerNorm ----------------
__global__ void build_tq(const float* __restrict__ feat,
                         const float* __restrict__ lnw, const float* __restrict__ lnb) {
    int warp = threadIdx.x / 32, lane = threadIdx.x % 32;
    int qg = blockIdx.x * 8 + warp;
    int b = qg / MQ;
    int q = qg % MQ;
    int w = q / 16, t = q % 16;
    int wy = w / 16, wx = w % 16;
    float vals[8];
    float sum = 0.f;
#pragma unroll
    for (int i = 0; i < 8; i++) {
        int c  = lane + i * 32;
        int ch = t * 16 + c / 16;
        int iy = (c / 4) % 4;
        int ix = c % 4;
        int y  = wy * 4 + iy, x = wx * 4 + ix;
        float v = feat[(((size_t)b * 256 + ch) * 64 + y) * 64 + x];
        vals[i] = v; sum += v;
    }
#pragma unroll
    for (int o = 16; o; o >>= 1) sum += __shfl_xor_sync(0xffffffffu, sum, o);
    float mu = sum * (1.f / 256.f);
    float vs = 0.f;
#pragma unroll
    for (int i = 0; i < 8; i++) { float d = vals[i] - mu; vs += d * d; }
#pragma unroll
    for (int o = 16; o; o >>= 1) vs += __shfl_xor_sync(0xffffffffu, vs, o);
    float rstd = rsqrtf(vs * (1.f / 256.f) + 1e-5f);
#pragma unroll
    for (int i = 0; i < 8; i++) {
        int c = lane + i * 32;
        g_tq[(size_t)qg * 256 + c] = (vals[i] - mu) * rstd * lnw[c] + lnb[c];
    }
}

// ---------------- 2) local tokens: gather (zero-padded) ----------------
__global__ void build_tloc(const float* __restrict__ feat) {
    int idx = blockIdx.x * 256 + threadIdx.x;
    int c   = idx % 256;
    int row = idx / 256;
    int b   = row / MLOC;
    int wt  = row % MLOC;
    int w   = wt / 64, t = wt % 64;
    int ch  = t * 4 + c / 64;
    int iy  = (c / 8) % 8;
    int ix  = c % 8;
    int y   = (w / 16) * 4 + iy - 2;
    int x   = (w % 16) * 4 + ix - 2;
    float v = 0.f;
    if ((unsigned)y < 64u && (unsigned)x < 64u)
        v = feat[(((size_t)b * 256 + ch) * 64 + y) * 64 + x];
    g_tloc[idx] = v;
}

// ---------------- 3) mid/glb pooled tokens ----------------
__global__ void build_tmg(const float* __restrict__ feat) {
    int l = blockIdx.x, b = blockIdx.y, c = threadIdx.x;
    const float* f = feat + ((size_t)b * 256 + c) * 4096;
    float v;
    if (l < 1024) {
        int y = l / 32, x = l % 32;
        v = 0.25f * (f[(2 * y) * 64 + 2 * x]     + f[(2 * y) * 64 + 2 * x + 1] +
                     f[(2 * y + 1) * 64 + 2 * x] + f[(2 * y + 1) * 64 + 2 * x + 1]);
    } else {
        int g = l - 1024;
        int y = g / 16, x = g % 16;
        float s = 0.f;
#pragma unroll
        for (int dy = 0; dy < 4; dy++)
#pragma unroll
            for (int dx = 0; dx < 4; dx++) s += f[(4 * y + dy) * 64 + 4 * x + dx];
        v = 0.0625f * s;
    }
    g_tmg[((size_t)b * MG + l) * 256 + c] = v;
}

// ---------------- 4) unified projection GEMM (capped regs -> 2 blocks/SM) ----------------
__global__ void __launch_bounds__(256, 2) gemm_all(
    const float* __restrict__ Wm, const float* __restrict__ bias)
{
    int id = blockIdx.x;
    int sel, Mrows, wcol0, ldc, nn;
    if (id < 1024)      { sel = 1; Mrows = MLOC; wcol0 = 256; ldc = 512; nn = 4; }            // loc KV
    else if (id < 1152) { sel = 0; id -= 1024; Mrows = MQ;  wcol0 = 0;   ldc = 256; nn = 2; } // Q
    else                { sel = 2; id -= 1152; Mrows = MG;  wcol0 = 256; ldc = 512; nn = 4; } // mg KV
    int per_b = (Mrows / 128) * nn;
    int b  = id / per_b;
    int r  = id % per_b;
    int mt = r / nn, nt = r % nn;
    const int m0 = mt * 128, n0 = nt * 128;
    const float* Ab = in_ptr(sel) + (size_t)b * Mrows * 256;
    float* Cb = out_ptr(sel) + (size_t)b * Mrows * ldc;

    __shared__ float As[16][129];   // [k][m]
    __shared__ float Bs[16][128];   // [k][n]
    const int tid = threadIdx.x;
    const int tx = tid & 15, ty = tid >> 4;
    u64 acc2[8][4];
#pragma unroll
    for (int i = 0; i < 8; i++)
#pragma unroll
        for (int j = 0; j < 4; j++) acc2[i][j] = 0ull;

    for (int k0 = 0; k0 < 256; k0 += 16) {
#pragma unroll
        for (int i = 0; i < 8; i++) {
            int flat = tid + i * 256;
            int mm = flat >> 4, kk = flat & 15;
            As[kk][mm] = Ab[(size_t)(m0 + mm) * 256 + k0 + kk];
        }
#pragma unroll
        for (int i = 0; i < 8; i++) {
            int flat = tid + i * 256;
            int kk = flat >> 7, nnq = flat & 127;
            Bs[kk][nnq] = Wm[(size_t)(k0 + kk) * 768 + wcol0 + n0 + nnq];
        }
        __syncthreads();
#pragma unroll
        for (int k = 0; k < 16; k++) {
            u64 b2[4];
#pragma unroll
            for (int jp = 0; jp < 4; jp++)
                b2[jp] = *(const u64*)&Bs[k][2 * tx + 32 * jp];
#pragma unroll
            for (int i = 0; i < 8; i++) {
                float a = As[k][ty * 8 + i];
                u64 a2 = pack2(a, a);
#pragma unroll
                for (int jp = 0; jp < 4; jp++)
                    acc2[i][jp] = ffma2(a2, b2[jp], acc2[i][jp]);
            }
        }
        __syncthreads();
    }
#pragma unroll
    for (int i = 0; i < 8; i++) {
        int m = m0 + ty * 8 + i;
#pragma unroll
        for (int jp = 0; jp < 4; jp++) {
            int n = n0 + 2 * tx + 32 * jp;
            float c0, c1; unpack2(acc2[i][jp], c0, c1);
            float2 bv = *(const float2*)&bias[wcol0 + n];
            *(float2*)&Cb[(size_t)m * ldc + n] = make_float2(c0 + bv.x, c1 + bv.y);
        }
    }
}

// ---------------- 5) attention: per-head blocks, head-sliced K/V staging ----------------
// grid (qtile=32, head=8, b=2); 128 threads, thread = one query token, d=32 dims of `head`
#define NCH 48
__global__ void __launch_bounds__(128) attn_kernel() {
    const int tid   = threadIdx.x;
    const int qtile = blockIdx.x;
    const int head  = blockIdx.y;
    const int b     = blockIdx.z;
    const int wbase = qtile * 8;
    const int win   = tid >> 4;             // this thread's window within the 8
    const int q     = qtile * 128 + tid;    // query token in batch

    __shared__ __align__(16) float sbuf[2][4096];   // 2 x 16 KB ping-pong

    const float4* qp = (const float4*)(g_q + ((size_t)(b * MQ + q) * 256 + head * 32));
    // pre-scale by 1/sqrt(32) * log2(e): dot product then yields log2-domain score
    const float scale = 0.17677669529663687f * 1.4426950408889634f;
    u64 q2[16];
#pragma unroll
    for (int j = 0; j < 8; j++) {
        float4 qv = qp[j];
        q2[2 * j]     = pack2(qv.x * scale, qv.y * scale);
        q2[2 * j + 1] = pack2(qv.z * scale, qv.w * scale);
    }
    float l = 0.f;
    u64 acc2[16];
#pragma unroll
    for (int j = 0; j < 16; j++) acc2[j] = 0ull;

    const float4* kvloc4 = (const float4*)g_kvloc;
    const float4* kvmg4  = (const float4*)g_kvmg;
    const int head8 = head * 8;
    const int bML = b * MLOC, bMG = b * MG;
    uint32_t sbase[2] = { (uint32_t)__cvta_generic_to_shared(&sbuf[0][0]),
                          (uint32_t)__cvta_generic_to_shared(&sbuf[1][0]) };

#define ISSUE(ch, buf) do {                                                              \
        uint32_t sb_ = sbase[buf];                                                       \
        if ((ch) < 8) {                                                                  \
            _Pragma("unroll")                                                            \
            for (int j_ = 0; j_ < 8; j_++) {                                             \
                int idx_ = tid + j_ * 128;                                               \
                int slot_ = idx_ >> 4, j4_ = idx_ & 15;                                  \
                int grow_ = (wbase + (slot_ >> 3)) * 64 + (ch) * 8 + (slot_ & 7);        \
                int col_ = (j4_ < 8) ? head8 + j4_ : 64 + head8 + (j4_ - 8);             \
                asm volatile("cp.async.cg.shared.global [%0], [%1], 16;"                 \
                    :: "r"(sb_ + idx_ * 16),                                             \
                       "l"(kvloc4 + (size_t)(bML + grow_) * 128 + col_));                \
            }                                                                            \
        } else {                                                                         \
            _Pragma("unroll")                                                            \
            for (int j_ = 0; j_ < 4; j_++) {                                             \
                int idx_ = tid + j_ * 128;                                               \
                int key_ = idx_ >> 4, j4_ = idx_ & 15;                                   \
                int grow_ = bMG + ((ch) - 8) * 32 + key_;                                \
                int col_ = (j4_ < 8) ? head8 + j4_ : 64 + head8 + (j4_ - 8);             \
                asm volatile("cp.async.cg.shared.global [%0], [%1], 16;"                 \
                    :: "r"(sb_ + idx_ * 16),                                             \
                       "l"(kvmg4 + (size_t)grow_ * 128 + col_));                         \
            }                                                                            \
        }                                                                                \
        asm volatile("cp.async.commit_group;");                                         \
    } while (0)

    ISSUE(0, 0);
    for (int ch = 0; ch < NCH; ch++) {
        if (ch + 1 < NCH) {
            ISSUE(ch + 1, (ch + 1) & 1);
            asm volatile("cp.async.wait_group 1;" ::: "memory");
        } else {
            asm volatile("cp.async.wait_group 0;" ::: "memory");
        }
        __syncthreads();
        const float* base = &sbuf[ch & 1][0];
        const float* kptr0;
        int nk;
        if (ch < 8) { kptr0 = base + (win * 8) * 64; nk = 8; }
        else        { kptr0 = base;                  nk = 32; }
#pragma unroll 8
        for (int kk = 0; kk < nk; kk++) {
            const float* kp = kptr0 + kk * 64;
            const ulonglong2* krow = (const ulonglong2*)kp;
            u64 sa = 0ull, sb2 = 0ull, sc = 0ull, sd = 0ull;
#pragma unroll
            for (int j = 0; j < 4; j++) {
                ulonglong2 k0 = krow[2 * j];
                ulonglong2 k1 = krow[2 * j + 1];
                sa  = ffma2(q2[4 * j],     k0.x, sa);
                sb2 = ffma2(q2[4 * j + 1], k0.y, sb2);
                sc  = ffma2(q2[4 * j + 2], k1.x, sc);
                sd  = ffma2(q2[4 * j + 3], k1.y, sd);
            }
            // packed reduction tree: 3 add2 + 1 unpack + 1 add
            u64 t2 = add2(add2(sa, sb2), add2(sc, sd));
            float e0, e1; unpack2(t2, e0, e1);
            float wgt = ex2(e0 + e1);         // score already in log2 domain
            l += wgt;
            u64 w2 = pack2(wgt, wgt);
            const ulonglong2* vrow = (const ulonglong2*)(kp + 32);
#pragma unroll
            for (int j = 0; j < 8; j++) {
                ulonglong2 v = vrow[j];
                acc2[2 * j]     = ffma2(w2, v.x, acc2[2 * j]);
                acc2[2 * j + 1] = ffma2(w2, v.y, acc2[2 * j + 1]);
            }
        }
        __syncthreads();
    }

    float inv = 1.0f / l;
    float4* op = (float4*)(g_ao + ((size_t)(b * MQ + q) * 256 + head * 32));
#pragma unroll
    for (int j = 0; j < 8; j++) {
        float x0, x1, x2, x3;
        unpack2(acc2[2 * j], x0, x1);
        unpack2(acc2[2 * j + 1], x2, x3);
        op[j] = make_float4(x0 * inv, x1 * inv, x2 * inv, x3 * inv);
    }
}

// ---------------- 6) output projection + scatter + residual ----------------
__global__ void __launch_bounds__(256, 2) gemm_out(
    const float* __restrict__ feat, float* __restrict__ out,
    const float* __restrict__ Wm, const float* __restrict__ bias)
{
    const int m0 = blockIdx.x * 128, n0 = blockIdx.y * 128, b = blockIdx.z;
    const float* Ab = g_ao + (size_t)b * MQ * 256;
    __shared__ float As[16][129];
    __shared__ float Bs[16][128];
    const int tid = threadIdx.x;
    const int tx = tid & 15, ty = tid >> 4;
    u64 acc2[8][4];
#pragma unroll
    for (int i = 0; i < 8; i++)
#pragma unroll
        for (int j = 0; j < 4; j++) acc2[i][j] = 0ull;

    for (int k0 = 0; k0 < 256; k0 += 16) {
#pragma unroll
        for (int i = 0; i < 8; i++) {
            int flat = tid + i * 256;
            int mm = flat >> 4, kk = flat & 15;
            As[kk][mm] = Ab[(size_t)(m0 + mm) * 256 + k0 + kk];
        }
#pragma unroll
        for (int i = 0; i < 8; i++) {
            int flat = tid + i * 256;
            int kk = flat >> 7, nnq = flat & 127;
            Bs[kk][nnq] = Wm[(size_t)(k0 + kk) * 256 + n0 + nnq];
        }
        __syncthreads();
#pragma unroll
        for (int k = 0; k < 16; k++) {
            u64 b2[4];
#pragma unroll
            for (int jp = 0; jp < 4; jp++)
                b2[jp] = *(const u64*)&Bs[k][2 * tx + 32 * jp];
#pragma unroll
            for (int i = 0; i < 8; i++) {
                float a = As[k][ty * 8 + i];
                u64 a2 = pack2(a, a);
#pragma unroll
                for (int jp = 0; jp < 4; jp++)
                    acc2[i][jp] = ffma2(a2, b2[jp], acc2[i][jp]);
            }
        }
        __syncthreads();
    }
#pragma unroll
    for (int i = 0; i < 8; i++) {
        int q = m0 + ty * 8 + i;
        int w = q / 16, t = q % 16;
        int y = (w / 16) * 4 + t / 4;
        int x = (w % 16) * 4 + t % 4;
        int pix = y * 64 + x;
#pragma unroll
        for (int jp = 0; jp < 4; jp++) {
            int n = n0 + 2 * tx + 32 * jp;
            float c0, c1; unpack2(acc2[i][jp], c0, c1);
            size_t o0 = (((size_t)b * 256 + n) << 12) + pix;
            size_t o1 = o0 + 4096;
            out[o0] = c0 + bias[n] + feat[o0];
            out[o1] = c1 + bias[n + 1] + feat[o1];
        }
    }
}

// ---------------- launch (only harness pointers cross host->device) ----------------
extern "C" void kernel_launch(void* const* d_in, const int* in_sizes, int n_in,
                              void* d_out, int out_size) {
    const float* feat  = (const float*)d_in[0];
    const float* qkv_w = (const float*)d_in[1];
    const float* qkv_b = (const float*)d_in[2];
    const float* out_w = (const float*)d_in[3];
    const float* out_b = (const float*)d_in[4];
    const float* ln_w  = (const float*)d_in[5];
    const float* ln_b  = (const float*)d_in[6];
    float* out = (float*)d_out;

    build_tq  <<<(B_ * MQ) / 8, 256>>>(feat, ln_w, ln_b);
    build_tloc<<<(int)(((size_t)B_ * MLOC * 256) / 256), 256>>>(feat);
    build_tmg <<<dim3(MG, B_), 256>>>(feat);

    gemm_all<<<1232, 256>>>(qkv_w, qkv_b);

    attn_kernel<<<dim3(32, 8, B_), 128>>>();

    gemm_out<<<dim3(MQ / 128, 256 / 128, B_), 256>>>(feat, out, out_w, out_b);
}

// round 15
// speedup vs baseline: 2.3551x; 1.3349x over previous
#include <cuda_runtime.h>
#include <cuda_bf16.h>
#include <cstdint>

#define B_   2
#define C_   256
#define MLOC 16384
#define MQ   4096
#define MG   1280
#define NW   256
#define LK   1344

typedef unsigned long long u64;

// ---------------- scratch (device globals; ONLY referenced from device code) ----------------
__device__ __nv_bfloat16 g_tq  [B_ * MQ * C_];
__device__ __nv_bfloat16 g_tloc[(size_t)B_ * MLOC * C_];
__device__ __nv_bfloat16 g_tmg [B_ * MG * C_];
__device__ __nv_bfloat16 g_wT  [768 * 256];          // qkv_w transposed: [n][k] bf16
__device__ float g_q    [B_ * MQ * C_];
__device__ float g_kvloc[(size_t)B_ * MLOC * 512];   // K+bias:0..255, V+bias:256..511
__device__ float g_kvmg [B_ * MG * 512];
__device__ float g_ao   [B_ * MQ * C_];

// Device-side pointer selection — NEVER pass __device__ symbols from host code
// (on GB300, host-shadow addresses are ATS-dereferenceable and fail silently).
__device__ __forceinline__ const __nv_bfloat16* in_ptr(int id) {
    switch (id) { case 0: return g_tq; case 1: return g_tloc; default: return g_tmg; }
}
__device__ __forceinline__ float* out_ptr(int id) {
    switch (id) { case 0: return g_q; case 1: return g_kvloc; default: return g_kvmg; }
}

// ---------------- packed f32x2 primitives ----------------
__device__ __forceinline__ u64 pack2(float a, float b) {
    u64 r; asm("mov.b64 %0, {%1, %2};" : "=l"(r) : "f"(a), "f"(b)); return r;
}
__device__ __forceinline__ void unpack2(u64 v, float& a, float& b) {
    asm("mov.b64 {%0, %1}, %2;" : "=f"(a), "=f"(b) : "l"(v));
}
__device__ __forceinline__ u64 ffma2(u64 a, u64 b, u64 c) {
    u64 d; asm("fma.rn.f32x2 %0, %1, %2, %3;" : "=l"(d) : "l"(a), "l"(b), "l"(c)); return d;
}
__device__ __forceinline__ u64 add2(u64 a, u64 b) {
    u64 d; asm("add.rn.f32x2 %0, %1, %2;" : "=l"(d) : "l"(a), "l"(b)); return d;
}
__device__ __forceinline__ float ex2(float x) {
    float r; asm("ex2.approx.f32 %0, %1;" : "=f"(r) : "f"(x)); return r;
}

// ---------------- baseline tensor-core primitives (sm_80+, no feature suffix) ----------------
__device__ __forceinline__ uint32_t smem_u32(const void* p) {
    uint32_t a;
    asm("{ .reg .u64 t; cvta.to.shared.u64 t, %1; cvt.u32.u64 %0, t; }" : "=r"(a) : "l"(p));
    return a;
}
__device__ __forceinline__ void ldsm4(uint32_t* r, uint32_t addr) {
    asm volatile("ldmatrix.sync.aligned.m8n8.x4.shared.b16 {%0,%1,%2,%3}, [%4];"
                 : "=r"(r[0]), "=r"(r[1]), "=r"(r[2]), "=r"(r[3]) : "r"(addr));
}
__device__ __forceinline__ void mma16816(float* d, const uint32_t* a, uint32_t b0, uint32_t b1) {
    asm volatile("mma.sync.aligned.m16n8k16.row.col.f32.bf16.bf16.f32 "
                 "{%0,%1,%2,%3}, {%4,%5,%6,%7}, {%8,%9}, {%0,%1,%2,%3};"
                 : "+f"(d[0]), "+f"(d[1]), "+f"(d[2]), "+f"(d[3])
                 : "r"(a[0]), "r"(a[1]), "r"(a[2]), "r"(a[3]), "r"(b0), "r"(b1));
}

// ---------------- 1) query tokens: gather + LayerNorm -> bf16 ----------------
__global__ void build_tq(const float* __restrict__ feat,
                         const float* __restrict__ lnw, const float* __restrict__ lnb) {
    int warp = threadIdx.x / 32, lane = threadIdx.x % 32;
    int qg = blockIdx.x * 8 + warp;
    int b = qg / MQ;
    int q = qg % MQ;
    int w = q / 16, t = q % 16;
    int wy = w / 16, wx = w % 16;
    float vals[8];
    float sum = 0.f;
#pragma unroll
    for (int i = 0; i < 8; i++) {
        int c  = lane + i * 32;
        int ch = t * 16 + c / 16;
        int iy = (c / 4) % 4;
        int ix = c % 4;
        int y  = wy * 4 + iy, x = wx * 4 + ix;
        float v = feat[(((size_t)b * 256 + ch) * 64 + y) * 64 + x];
        vals[i] = v; sum += v;
    }
#pragma unroll
    for (int o = 16; o; o >>= 1) sum += __shfl_xor_sync(0xffffffffu, sum, o);
    float mu = sum * (1.f / 256.f);
    float vs = 0.f;
#pragma unroll
    for (int i = 0; i < 8; i++) { float d = vals[i] - mu; vs += d * d; }
#pragma unroll
    for (int o = 16; o; o >>= 1) vs += __shfl_xor_sync(0xffffffffu, vs, o);
    float rstd = rsqrtf(vs * (1.f / 256.f) + 1e-5f);
#pragma unroll
    for (int i = 0; i < 8; i++) {
        int c = lane + i * 32;
        g_tq[(size_t)qg * 256 + c] = __float2bfloat16((vals[i] - mu) * rstd * lnw[c] + lnb[c]);
    }
}

// ---------------- 2) local tokens: gather (zero-padded) -> bf16 ----------------
__global__ void build_tloc(const float* __restrict__ feat) {
    int idx = blockIdx.x * 256 + threadIdx.x;
    int c   = idx % 256;
    int row = idx / 256;
    int b   = row / MLOC;
    int wt  = row % MLOC;
    int w   = wt / 64, t = wt % 64;
    int ch  = t * 4 + c / 64;
    int iy  = (c / 8) % 8;
    int ix  = c % 8;
    int y   = (w / 16) * 4 + iy - 2;
    int x   = (w % 16) * 4 + ix - 2;
    float v = 0.f;
    if ((unsigned)y < 64u && (unsigned)x < 64u)
        v = feat[(((size_t)b * 256 + ch) * 64 + y) * 64 + x];
    g_tloc[idx] = __float2bfloat16(v);
}

// ---------------- 3) mid/glb pooled tokens -> bf16 ----------------
__global__ void build_tmg(const float* __restrict__ feat) {
    int l = blockIdx.x, b = blockIdx.y, c = threadIdx.x;
    const float* f = feat + ((size_t)b * 256 + c) * 4096;
    float v;
    if (l < 1024) {
        int y = l / 32, x = l % 32;
        v = 0.25f * (f[(2 * y) * 64 + 2 * x]     + f[(2 * y) * 64 + 2 * x + 1] +
                     f[(2 * y + 1) * 64 + 2 * x] + f[(2 * y + 1) * 64 + 2 * x + 1]);
    } else {
        int g = l - 1024;
        int y = g / 16, x = g % 16;
        float s = 0.f;
#pragma unroll
        for (int dy = 0; dy < 4; dy++)
#pragma unroll
            for (int dx = 0; dx < 4; dx++) s += f[(4 * y + dy) * 64 + 4 * x + dx];
        v = 0.0625f * s;
    }
    g_tmg[((size_t)b * MG + l) * 256 + c] = __float2bfloat16(v);
}

// ---------------- 3b) transpose qkv_w -> bf16 [n][k] ----------------
__global__ void build_wT(const float* __restrict__ qkv_w) {
    int idx = blockIdx.x * 256 + threadIdx.x;   // 768*256 total
    int n = idx / 256, k = idx % 256;
    g_wT[idx] = __float2bfloat16(qkv_w[(size_t)k * 768 + n]);
}

// ---------------- 4) projection GEMM via mma.sync bf16 (tensor pipe) ----------------
// 128x128x256 tile; 8 warps (4x2), warp tile 32x64; K in 4 chunks of 64.
#define LDS_STRIDE 72   // bf16 elems per smem row (144B): ldmatrix banks 4r mod 32, conflict-free
__global__ void __launch_bounds__(256, 2) gemm_all_mma(const float* __restrict__ bias) {
    int id = blockIdx.x;
    int sel, Mrows, wcol0, ldc, nn;
    if (id < 1024)      { sel = 1; Mrows = MLOC; wcol0 = 256; ldc = 512; nn = 4; }
    else if (id < 1152) { sel = 0; id -= 1024; Mrows = MQ;  wcol0 = 0;   ldc = 256; nn = 2; }
    else                { sel = 2; id -= 1152; Mrows = MG;  wcol0 = 256; ldc = 512; nn = 4; }
    int per_b = (Mrows / 128) * nn;
    int b  = id / per_b;
    int r  = id % per_b;
    int m0 = (r / nn) * 128, n0 = (r % nn) * 128;

    __shared__ __align__(16) __nv_bfloat16 As[128 * LDS_STRIDE];
    __shared__ __align__(16) __nv_bfloat16 Bs[128 * LDS_STRIDE];

    const int tid = threadIdx.x;
    const int warp = tid >> 5, lane = tid & 31;
    const int wy = warp >> 1, wx = warp & 1;     // wy: m quadrant, wx: n half

    float acc[2][8][4];
#pragma unroll
    for (int i = 0; i < 2; i++)
#pragma unroll
        for (int j = 0; j < 8; j++)
#pragma unroll
            for (int t = 0; t < 4; t++) acc[i][j][t] = 0.f;

    const __nv_bfloat16* Asrc = in_ptr(sel) + ((size_t)b * Mrows + m0) * 256;
    const __nv_bfloat16* Bsrc = g_wT + (size_t)(wcol0 + n0) * 256;

    uint32_t as_base = smem_u32(As), bs_base = smem_u32(Bs);
    // per-lane ldmatrix row/col selects
    const int arow    = wy * 32 + (lane & 7) + ((lane >> 3) & 1) * 8;
    const int acolsel = (lane >> 4);         // 0/1 -> +8 k
    const int brow    = wx * 64 + (lane & 7) + ((lane >> 4) & 1) * 8;
    const int bksel   = (lane >> 3) & 1;     // 0/1 -> +8 k

    for (int kc = 0; kc < 4; kc++) {
#pragma unroll
        for (int i = 0; i < 4; i++) {
            int idx = tid + i * 256;
            int rr = idx >> 3, c8 = (idx & 7) * 8;
            *(uint4*)&As[rr * LDS_STRIDE + c8] = *(const uint4*)(Asrc + (size_t)rr * 256 + kc * 64 + c8);
            *(uint4*)&Bs[rr * LDS_STRIDE + c8] = *(const uint4*)(Bsrc + (size_t)rr * 256 + kc * 64 + c8);
        }
        __syncthreads();
#pragma unroll
        for (int ks = 0; ks < 4; ks++) {
            int kb = ks * 16;
            uint32_t af[2][4];
#pragma unroll
            for (int mt = 0; mt < 2; mt++)
                ldsm4(af[mt], as_base + ((arow + mt * 16) * LDS_STRIDE + kb + acolsel * 8) * 2);
            uint32_t bf[4][4];
#pragma unroll
            for (int p = 0; p < 4; p++)
                ldsm4(bf[p], bs_base + ((brow + p * 16) * LDS_STRIDE + kb + bksel * 8) * 2);
#pragma unroll
            for (int mt = 0; mt < 2; mt++)
#pragma unroll
                for (int p = 0; p < 4; p++) {
                    mma16816(acc[mt][2 * p],     af[mt], bf[p][0], bf[p][1]);
                    mma16816(acc[mt][2 * p + 1], af[mt], bf[p][2], bf[p][3]);
                }
        }
        __syncthreads();
    }

    // epilogue: scattered float2 stores + bias
    float* Cb = out_ptr(sel) + (size_t)b * Mrows * ldc;
#pragma unroll
    for (int mt = 0; mt < 2; mt++) {
        int m = m0 + wy * 32 + mt * 16 + lane / 4;
#pragma unroll
        for (int nt = 0; nt < 8; nt++) {
            int n = n0 + wx * 64 + nt * 8 + 2 * (lane & 3);
            float2 bv = *(const float2*)&bias[wcol0 + n];
            *(float2*)&Cb[(size_t)m * ldc + n] =
                make_float2(acc[mt][nt][0] + bv.x, acc[mt][nt][1] + bv.y);
            *(float2*)&Cb[(size_t)(m + 8) * ldc + n] =
                make_float2(acc[mt][nt][2] + bv.x, acc[mt][nt][3] + bv.y);
        }
    }
}

// ---------------- 5) attention: per-head blocks, head-sliced K/V staging (R13-proven) ----------------
#define NCH 48
__global__ void __launch_bounds__(128) attn_kernel() {
    const int tid   = threadIdx.x;
    const int qtile = blockIdx.x;
    const int head  = blockIdx.y;
    const int b     = blockIdx.z;
    const int wbase = qtile * 8;
    const int win   = tid >> 4;
    const int q     = qtile * 128 + tid;

    __shared__ __align__(16) float sbuf[2][4096];

    const float4* qp = (const float4*)(g_q + ((size_t)(b * MQ + q) * 256 + head * 32));
    const float scale = 0.17677669529663687f * 1.4426950408889634f;
    u64 q2[16];
#pragma unroll
    for (int j = 0; j < 8; j++) {
        float4 qv = qp[j];
        q2[2 * j]     = pack2(qv.x * scale, qv.y * scale);
        q2[2 * j + 1] = pack2(qv.z * scale, qv.w * scale);
    }
    float l = 0.f;
    u64 acc2[16];
#pragma unroll
    for (int j = 0; j < 16; j++) acc2[j] = 0ull;

    const float4* kvloc4 = (const float4*)g_kvloc;
    const float4* kvmg4  = (const float4*)g_kvmg;
    const int head8 = head * 8;
    const int bML = b * MLOC, bMG = b * MG;
    uint32_t sbase[2] = { (uint32_t)__cvta_generic_to_shared(&sbuf[0][0]),
                          (uint32_t)__cvta_generic_to_shared(&sbuf[1][0]) };

#define ISSUE(ch, buf) do {                                                              \
        uint32_t sb_ = sbase[buf];                                                       \
        if ((ch) < 8) {                                                                  \
            _Pragma("unroll")                                                            \
            for (int j_ = 0; j_ < 8; j_++) {                                             \
                int idx_ = tid + j_ * 128;                                               \
                int slot_ = idx_ >> 4, j4_ = idx_ & 15;                                  \
                int grow_ = (wbase + (slot_ >> 3)) * 64 + (ch) * 8 + (slot_ & 7);        \
                int col_ = (j4_ < 8) ? head8 + j4_ : 64 + head8 + (j4_ - 8);             \
                asm volatile("cp.async.cg.shared.global [%0], [%1], 16;"                 \
                    :: "r"(sb_ + idx_ * 16),                                             \
                       "l"(kvloc4 + (size_t)(bML + grow_) * 128 + col_));                \
            }                                                                            \
        } else {                                                                         \
            _Pragma("unroll")                                                            \
            for (int j_ = 0; j_ < 4; j_++) {                                             \
                int idx_ = tid + j_ * 128;                                               \
                int key_ = idx_ >> 4, j4_ = idx_ & 15;                                   \
                int grow_ = bMG + ((ch) - 8) * 32 + key_;                                \
                int col_ = (j4_ < 8) ? head8 + j4_ : 64 + head8 + (j4_ - 8);             \
                asm volatile("cp.async.cg.shared.global [%0], [%1], 16;"                 \
                    :: "r"(sb_ + idx_ * 16),                                             \
                       "l"(kvmg4 + (size_t)grow_ * 128 + col_));                         \
            }                                                                            \
        }                                                                                \
        asm volatile("cp.async.commit_group;");                                         \
    } while (0)

    ISSUE(0, 0);
    for (int ch = 0; ch < NCH; ch++) {
        if (ch + 1 < NCH) {
            ISSUE(ch + 1, (ch + 1) & 1);
            asm volatile("cp.async.wait_group 1;" ::: "memory");
        } else {
            asm volatile("cp.async.wait_group 0;" ::: "memory");
        }
        __syncthreads();
        const float* base = &sbuf[ch & 1][0];
        const float* kptr0;
        int nk;
        if (ch < 8) { kptr0 = base + (win * 8) * 64; nk = 8; }
        else        { kptr0 = base;                  nk = 32; }
#pragma unroll 8
        for (int kk = 0; kk < nk; kk++) {
            const float* kp = kptr0 + kk * 64;
            const ulonglong2* krow = (const ulonglong2*)kp;
            u64 sa = 0ull, sb2 = 0ull, sc = 0ull, sd = 0ull;
#pragma unroll
            for (int j = 0; j < 4; j++) {
                ulonglong2 k0 = krow[2 * j];
                ulonglong2 k1 = krow[2 * j + 1];
                sa  = ffma2(q2[4 * j],     k0.x, sa);
                sb2 = ffma2(q2[4 * j + 1], k0.y, sb2);
                sc  = ffma2(q2[4 * j + 2], k1.x, sc);
                sd  = ffma2(q2[4 * j + 3], k1.y, sd);
            }
            u64 t2 = add2(add2(sa, sb2), add2(sc, sd));
            float e0, e1; unpack2(t2, e0, e1);
            float wgt = ex2(e0 + e1);
            l += wgt;
            u64 w2 = pack2(wgt, wgt);
            const ulonglong2* vrow = (const ulonglong2*)(kp + 32);
#pragma unroll
            for (int j = 0; j < 8; j++) {
                ulonglong2 v = vrow[j];
                acc2[2 * j]     = ffma2(w2, v.x, acc2[2 * j]);
                acc2[2 * j + 1] = ffma2(w2, v.y, acc2[2 * j + 1]);
            }
        }
        __syncthreads();
    }

    float inv = 1.0f / l;
    float4* op = (float4*)(g_ao + ((size_t)(b * MQ + q) * 256 + head * 32));
#pragma unroll
    for (int j = 0; j < 8; j++) {
        float x0, x1, x2, x3;
        unpack2(acc2[2 * j], x0, x1);
        unpack2(acc2[2 * j + 1], x2, x3);
        op[j] = make_float4(x0 * inv, x1 * inv, x2 * inv, x3 * inv);
    }
}

// ---------------- 6) output projection + scatter + residual (FFMA2, proven) ----------------
__global__ void __launch_bounds__(256, 2) gemm_out(
    const float* __restrict__ feat, float* __restrict__ out,
    const float* __restrict__ Wm, const float* __restrict__ bias)
{
    const int m0 = blockIdx.x * 128, n0 = blockIdx.y * 128, b = blockIdx.z;
    const float* Ab = g_ao + (size_t)b * MQ * 256;
    __shared__ float As[16][129];
    __shared__ float Bs[16][128];
    const int tid = threadIdx.x;
    const int tx = tid & 15, ty = tid >> 4;
    u64 acc2[8][4];
#pragma unroll
    for (int i = 0; i < 8; i++)
#pragma unroll
        for (int j = 0; j < 4; j++) acc2[i][j] = 0ull;

    for (int k0 = 0; k0 < 256; k0 += 16) {
#pragma unroll
        for (int i = 0; i < 8; i++) {
            int flat = tid + i * 256;
            int mm = flat >> 4, kk = flat & 15;
            As[kk][mm] = Ab[(size_t)(m0 + mm) * 256 + k0 + kk];
        }
#pragma unroll
        for (int i = 0; i < 8; i++) {
            int flat = tid + i * 256;
            int kk = flat >> 7, nnq = flat & 127;
            Bs[kk][nnq] = Wm[(size_t)(k0 + kk) * 256 + n0 + nnq];
        }
        __syncthreads();
#pragma unroll
        for (int k = 0; k < 16; k++) {
            u64 b2[4];
#pragma unroll
            for (int jp = 0; jp < 4; jp++)
                b2[jp] = *(const u64*)&Bs[k][2 * tx + 32 * jp];
#pragma unroll
            for (int i = 0; i < 8; i++) {
                float a = As[k][ty * 8 + i];
                u64 a2 = pack2(a, a);
#pragma unroll
                for (int jp = 0; jp < 4; jp++)
                    acc2[i][jp] = ffma2(a2, b2[jp], acc2[i][jp]);
            }
        }
        __syncthreads();
    }
#pragma unroll
    for (int i = 0; i < 8; i++) {
        int q = m0 + ty * 8 + i;
        int w = q / 16, t = q % 16;
        int y = (w / 16) * 4 + t / 4;
        int x = (w % 16) * 4 + t % 4;
        int pix = y * 64 + x;
#pragma unroll
        for (int jp = 0; jp < 4; jp++) {
            int n = n0 + 2 * tx + 32 * jp;
            float c0, c1; unpack2(acc2[i][jp], c0, c1);
            size_t o0 = (((size_t)b * 256 + n) << 12) + pix;
            size_t o1 = o0 + 4096;
            out[o0] = c0 + bias[n] + feat[o0];
            out[o1] = c1 + bias[n + 1] + feat[o1];
        }
    }
}

// ---------------- launch (only harness pointers cross host->device) ----------------
extern "C" void kernel_launch(void* const* d_in, const int* in_sizes, int n_in,
                              void* d_out, int out_size) {
    const float* feat  = (const float*)d_in[0];
    const float* qkv_w = (const float*)d_in[1];
    const float* qkv_b = (const float*)d_in[2];
    const float* out_w = (const float*)d_in[3];
    const float* out_b = (const float*)d_in[4];
    const float* ln_w  = (const float*)d_in[5];
    const float* ln_b  = (const float*)d_in[6];
    float* out = (float*)d_out;

    build_tq  <<<(B_ * MQ) / 8, 256>>>(feat, ln_w, ln_b);
    build_tloc<<<(int)(((size_t)B_ * MLOC * 256) / 256), 256>>>(feat);
    build_tmg <<<dim3(MG, B_), 256>>>(feat);
    build_wT  <<<768, 256>>>(qkv_w);

    gemm_all_mma<<<1232, 256>>>(qkv_b);

    attn_kernel<<<dim3(32, 8, B_), 128>>>();

    gemm_out<<<dim3(MQ / 128, 256 / 128, B_), 256>>>(feat, out, out_w, out_b);
}

// round 16
// speedup vs baseline: 5.9648x; 2.5327x over previous
#include <cuda_runtime.h>
#include <cuda_bf16.h>
#include <cstdint>

#define B_   2
#define C_   256
#define MLOC 16384
#define MQ   4096
#define MG   1280
#define NW   256
#define LK   1344

typedef unsigned long long u64;

// ---------------- scratch (device globals; ONLY referenced from device code) ----------------
__device__ __nv_bfloat16 g_tq  [B_ * MQ * C_];
__device__ __nv_bfloat16 g_tloc[(size_t)B_ * MLOC * C_];
__device__ __nv_bfloat16 g_tmg [B_ * MG * C_];
__device__ __nv_bfloat16 g_wT  [768 * 256];           // qkv_w transposed: [n][k] bf16
__device__ __nv_bfloat16 g_qb  [B_ * MQ * C_];        // Q (bias + scale*log2e folded), bf16
__device__ __nv_bfloat16 g_kvbl[(size_t)B_ * MLOC * 512];  // K:0..255 V:256..511 (bias incl), bf16
__device__ __nv_bfloat16 g_kvbm[B_ * MG * 512];
__device__ float g_ao   [B_ * MQ * C_];

// Device-side pointer selection — NEVER pass __device__ symbols from host code
// (on GB300, host-shadow addresses are ATS-dereferenceable and fail silently).
__device__ __forceinline__ const __nv_bfloat16* in_ptr(int id) {
    switch (id) { case 0: return g_tq; case 1: return g_tloc; default: return g_tmg; }
}
__device__ __forceinline__ __nv_bfloat16* outb_ptr(int id) {
    switch (id) { case 0: return g_qb; case 1: return g_kvbl; default: return g_kvbm; }
}

// ---------------- packed f32x2 primitives ----------------
__device__ __forceinline__ u64 pack2(float a, float b) {
    u64 r; asm("mov.b64 %0, {%1, %2};" : "=l"(r) : "f"(a), "f"(b)); return r;
}
__device__ __forceinline__ void unpack2(u64 v, float& a, float& b) {
    asm("mov.b64 {%0, %1}, %2;" : "=f"(a), "=f"(b) : "l"(v));
}
__device__ __forceinline__ u64 ffma2(u64 a, u64 b, u64 c) {
    u64 d; asm("fma.rn.f32x2 %0, %1, %2, %3;" : "=l"(d) : "l"(a), "l"(b), "l"(c)); return d;
}
__device__ __forceinline__ float ex2(float x) {
    float r; asm("ex2.approx.f32 %0, %1;" : "=f"(r) : "f"(x)); return r;
}
// pack two fp32 -> bf16x2 (lo = first arg)
__device__ __forceinline__ uint32_t cvtbf2(float lo, float hi) {
    uint32_t r; asm("cvt.rn.bf16x2.f32 %0, %1, %2;" : "=r"(r) : "f"(hi), "f"(lo)); return r;
}

// ---------------- baseline tensor-core primitives (sm_80+) ----------------
__device__ __forceinline__ uint32_t smem_u32(const void* p) {
    uint32_t a;
    asm("{ .reg .u64 t; cvta.to.shared.u64 t, %1; cvt.u32.u64 %0, t; }" : "=r"(a) : "l"(p));
    return a;
}
__device__ __forceinline__ void ldsm4(uint32_t* r, uint32_t addr) {
    asm volatile("ldmatrix.sync.aligned.m8n8.x4.shared.b16 {%0,%1,%2,%3}, [%4];"
                 : "=r"(r[0]), "=r"(r[1]), "=r"(r[2]), "=r"(r[3]) : "r"(addr));
}
__device__ __forceinline__ void ldsm4t(uint32_t* r, uint32_t addr) {
    asm volatile("ldmatrix.sync.aligned.m8n8.x4.trans.shared.b16 {%0,%1,%2,%3}, [%4];"
                 : "=r"(r[0]), "=r"(r[1]), "=r"(r[2]), "=r"(r[3]) : "r"(addr));
}
__device__ __forceinline__ void mma16816(float* d, const uint32_t* a, uint32_t b0, uint32_t b1) {
    asm volatile("mma.sync.aligned.m16n8k16.row.col.f32.bf16.bf16.f32 "
                 "{%0,%1,%2,%3}, {%4,%5,%6,%7}, {%8,%9}, {%0,%1,%2,%3};"
                 : "+f"(d[0]), "+f"(d[1]), "+f"(d[2]), "+f"(d[3])
                 : "r"(a[0]), "r"(a[1]), "r"(a[2]), "r"(a[3]), "r"(b0), "r"(b1));
}

// ---------------- 1) query tokens: gather + LayerNorm -> bf16 ----------------
__global__ void build_tq(const float* __restrict__ feat,
                         const float* __restrict__ lnw, const float* __restrict__ lnb) {
    int warp = threadIdx.x / 32, lane = threadIdx.x % 32;
    int qg = blockIdx.x * 8 + warp;
    int b = qg / MQ;
    int q = qg % MQ;
    int w = q / 16, t = q % 16;
    int wy = w / 16, wx = w % 16;
    float vals[8];
    float sum = 0.f;
#pragma unroll
    for (int i = 0; i < 8; i++) {
        int c  = lane + i * 32;
        int ch = t * 16 + c / 16;
        int iy = (c / 4) % 4;
        int ix = c % 4;
        int y  = wy * 4 + iy, x = wx * 4 + ix;
        float v = feat[(((size_t)b * 256 + ch) * 64 + y) * 64 + x];
        vals[i] = v; sum += v;
    }
#pragma unroll
    for (int o = 16; o; o >>= 1) sum += __shfl_xor_sync(0xffffffffu, sum, o);
    float mu = sum * (1.f / 256.f);
    float vs = 0.f;
#pragma unroll
    for (int i = 0; i < 8; i++) { float d = vals[i] - mu; vs += d * d; }
#pragma unroll
    for (int o = 16; o; o >>= 1) vs += __shfl_xor_sync(0xffffffffu, vs, o);
    float rstd = rsqrtf(vs * (1.f / 256.f) + 1e-5f);
#pragma unroll
    for (int i = 0; i < 8; i++) {
        int c = lane + i * 32;
        g_tq[(size_t)qg * 256 + c] = __float2bfloat16((vals[i] - mu) * rstd * lnw[c] + lnb[c]);
    }
}

// ---------------- 2) local tokens: gather (zero-padded) -> bf16 ----------------
__global__ void build_tloc(const float* __restrict__ feat) {
    int idx = blockIdx.x * 256 + threadIdx.x;
    int c   = idx % 256;
    int row = idx / 256;
    int b   = row / MLOC;
    int wt  = row % MLOC;
    int w   = wt / 64, t = wt % 64;
    int ch  = t * 4 + c / 64;
    int iy  = (c / 8) % 8;
    int ix  = c % 8;
    int y   = (w / 16) * 4 + iy - 2;
    int x   = (w % 16) * 4 + ix - 2;
    float v = 0.f;
    if ((unsigned)y < 64u && (unsigned)x < 64u)
        v = feat[(((size_t)b * 256 + ch) * 64 + y) * 64 + x];
    g_tloc[idx] = __float2bfloat16(v);
}

// ---------------- 3) mid/glb pooled tokens -> bf16 ----------------
__global__ void build_tmg(const float* __restrict__ feat) {
    int l = blockIdx.x, b = blockIdx.y, c = threadIdx.x;
    const float* f = feat + ((size_t)b * 256 + c) * 4096;
    float v;
    if (l < 1024) {
        int y = l / 32, x = l % 32;
        v = 0.25f * (f[(2 * y) * 64 + 2 * x]     + f[(2 * y) * 64 + 2 * x + 1] +
                     f[(2 * y + 1) * 64 + 2 * x] + f[(2 * y + 1) * 64 + 2 * x + 1]);
    } else {
        int g = l - 1024;
        int y = g / 16, x = g % 16;
        float s = 0.f;
#pragma unroll
        for (int dy = 0; dy < 4; dy++)
#pragma unroll
            for (int dx = 0; dx < 4; dx++) s += f[(4 * y + dy) * 64 + 4 * x + dx];
        v = 0.0625f * s;
    }
    g_tmg[((size_t)b * MG + l) * 256 + c] = __float2bfloat16(v);
}

// ---------------- 3b) transpose qkv_w -> bf16 [n][k] ----------------
__global__ void build_wT(const float* __restrict__ qkv_w) {
    int idx = blockIdx.x * 256 + threadIdx.x;
    int n = idx / 256, k = idx % 256;
    g_wT[idx] = __float2bfloat16(qkv_w[(size_t)k * 768 + n]);
}

// ---------------- 4) projection GEMM via mma.sync bf16 (R15-proven core; bf16 epilogue) ----------------
#define LDS_STRIDE 72
#define QSCL (0.17677669529663687f * 1.4426950408889634f)
__global__ void __launch_bounds__(256, 2) gemm_all_mma(const float* __restrict__ bias) {
    int id = blockIdx.x;
    int sel, Mrows, wcol0, ldc, nn;
    if (id < 1024)      { sel = 1; Mrows = MLOC; wcol0 = 256; ldc = 512; nn = 4; }
    else if (id < 1152) { sel = 0; id -= 1024; Mrows = MQ;  wcol0 = 0;   ldc = 256; nn = 2; }
    else                { sel = 2; id -= 1152; Mrows = MG;  wcol0 = 256; ldc = 512; nn = 4; }
    int per_b = (Mrows / 128) * nn;
    int b  = id / per_b;
    int r  = id % per_b;
    int m0 = (r / nn) * 128, n0 = (r % nn) * 128;

    __shared__ __align__(16) __nv_bfloat16 As[128 * LDS_STRIDE];
    __shared__ __align__(16) __nv_bfloat16 Bs[128 * LDS_STRIDE];

    const int tid = threadIdx.x;
    const int warp = tid >> 5, lane = tid & 31;
    const int wy = warp >> 1, wx = warp & 1;

    float acc[2][8][4];
#pragma unroll
    for (int i = 0; i < 2; i++)
#pragma unroll
        for (int j = 0; j < 8; j++)
#pragma unroll
            for (int t = 0; t < 4; t++) acc[i][j][t] = 0.f;

    const __nv_bfloat16* Asrc = in_ptr(sel) + ((size_t)b * Mrows + m0) * 256;
    const __nv_bfloat16* Bsrc = g_wT + (size_t)(wcol0 + n0) * 256;

    uint32_t as_base = smem_u32(As), bs_base = smem_u32(Bs);
    const int arow    = wy * 32 + (lane & 7) + ((lane >> 3) & 1) * 8;
    const int acolsel = (lane >> 4);
    const int brow    = wx * 64 + (lane & 7) + ((lane >> 4) & 1) * 8;
    const int bksel   = (lane >> 3) & 1;

    for (int kc = 0; kc < 4; kc++) {
#pragma unroll
        for (int i = 0; i < 4; i++) {
            int idx = tid + i * 256;
            int rr = idx >> 3, c8 = (idx & 7) * 8;
            *(uint4*)&As[rr * LDS_STRIDE + c8] = *(const uint4*)(Asrc + (size_t)rr * 256 + kc * 64 + c8);
            *(uint4*)&Bs[rr * LDS_STRIDE + c8] = *(const uint4*)(Bsrc + (size_t)rr * 256 + kc * 64 + c8);
        }
        __syncthreads();
#pragma unroll
        for (int ks = 0; ks < 4; ks++) {
            int kb = ks * 16;
            uint32_t af[2][4];
#pragma unroll
            for (int mt = 0; mt < 2; mt++)
                ldsm4(af[mt], as_base + ((arow + mt * 16) * LDS_STRIDE + kb + acolsel * 8) * 2);
            uint32_t bf[4][4];
#pragma unroll
            for (int p = 0; p < 4; p++)
                ldsm4(bf[p], bs_base + ((brow + p * 16) * LDS_STRIDE + kb + bksel * 8) * 2);
#pragma unroll
            for (int mt = 0; mt < 2; mt++)
#pragma unroll
                for (int p = 0; p < 4; p++) {
                    mma16816(acc[mt][2 * p],     af[mt], bf[p][0], bf[p][1]);
                    mma16816(acc[mt][2 * p + 1], af[mt], bf[p][2], bf[p][3]);
                }
        }
        __syncthreads();
    }

    // epilogue: bf16 stores (Q gets scale*log2e folded)
    __nv_bfloat16* obf = outb_ptr(sel);
    const float scl = (sel == 0) ? QSCL : 1.0f;
#pragma unroll
    for (int mt = 0; mt < 2; mt++) {
        int m = m0 + wy * 32 + mt * 16 + lane / 4;
#pragma unroll
        for (int nt = 0; nt < 8; nt++) {
            int n = n0 + wx * 64 + nt * 8 + 2 * (lane & 3);
            float2 bv = *(const float2*)&bias[wcol0 + n];
            *(uint32_t*)&obf[((size_t)b * Mrows + m) * ldc + n] =
                cvtbf2((acc[mt][nt][0] + bv.x) * scl, (acc[mt][nt][1] + bv.y) * scl);
            *(uint32_t*)&obf[((size_t)b * Mrows + m + 8) * ldc + n] =
                cvtbf2((acc[mt][nt][2] + bv.x) * scl, (acc[mt][nt][3] + bv.y) * scl);
        }
    }
}

// ---------------- 5) attention via mma.sync (FA2-style, direct softmax) ----------------
#define SROW 80          // padded smem row stride bytes (32 bf16 data + pad), conflict-free ldmatrix
#define QSM  0           // Q: 128 rows
#define LSM  10240       // local: warp w at LSM + w*10240, 2 bufs x 5120 (K 2560 | V 2560)
#define GSM  51200       // global: 2 bufs x 5120
#define ATTN_SMEM 61440

// process one staged 32-key chunk: K at ka, V at ka+2560. m-tiles [mt0, mt0+nmt)
__device__ __forceinline__ void attn_chunk(
    uint32_t ka, int lane, const uint32_t af[2][2][4],
    int mt0, int nmt, float o[2][4][4], float lsum[2][2])
{
    uint32_t va = ka + 2560;
    uint32_t bk[2][2][4];   // [keyhalf][kstep]
#pragma unroll
    for (int h = 0; h < 2; h++)
#pragma unroll
        for (int ks = 0; ks < 2; ks++)
            ldsm4(bk[h][ks], ka + (h * 16 + (lane & 7) + 8 * ((lane >> 4) & 1)) * SROW
                               + ks * 32 + 16 * ((lane >> 3) & 1));
    uint32_t bv[2][2][4];   // [keyhalf][dimhalf]
#pragma unroll
    for (int h = 0; h < 2; h++)
#pragma unroll
        for (int dh = 0; dh < 2; dh++)
            ldsm4t(bv[h][dh], va + (h * 16 + (lane & 7) + 8 * ((lane >> 3) & 1)) * SROW
                                + dh * 32 + 16 * ((lane >> 4) & 1));
#pragma unroll
    for (int mi = 0; mi < 2; mi++) {
        if (mi >= nmt) break;
        int mt = mt0 + mi;
        float c[4][4];
#pragma unroll
        for (int nt = 0; nt < 4; nt++)
#pragma unroll
            for (int t = 0; t < 4; t++) c[nt][t] = 0.f;
#pragma unroll
        for (int h = 0; h < 2; h++)
#pragma unroll
            for (int ks = 0; ks < 2; ks++) {
                mma16816(c[2 * h],     af[mt][ks], bk[h][ks][0], bk[h][ks][1]);
                mma16816(c[2 * h + 1], af[mt][ks], bk[h][ks][2], bk[h][ks][3]);
            }
        // direct softmax weights (scores already in log2 domain via folded Q scale)
#pragma unroll
        for (int nt = 0; nt < 4; nt++)
#pragma unroll
            for (int t = 0; t < 4; t++) {
                float e = ex2(c[nt][t]);
                lsum[mt][t >> 1] += e;
                c[nt][t] = e;
            }
        // P -> bf16 A-fragments (C-frag == A-frag register identity)
#pragma unroll
        for (int h = 0; h < 2; h++) {
            uint32_t pa[4];
            pa[0] = cvtbf2(c[2 * h][0],     c[2 * h][1]);
            pa[1] = cvtbf2(c[2 * h][2],     c[2 * h][3]);
            pa[2] = cvtbf2(c[2 * h + 1][0], c[2 * h + 1][1]);
            pa[3] = cvtbf2(c[2 * h + 1][2], c[2 * h + 1][3]);
#pragma unroll
            for (int dh = 0; dh < 2; dh++) {
                mma16816(o[mt][2 * dh],     pa, bv[h][dh][0], bv[h][dh][1]);
                mma16816(o[mt][2 * dh + 1], pa, bv[h][dh][2], bv[h][dh][3]);
            }
        }
    }
}

__global__ void __launch_bounds__(128) attn_mma() {
    extern __shared__ __align__(16) char sm[];
    const int tid = threadIdx.x, warp = tid >> 5, lane = tid & 31;
    const int qtile = blockIdx.x, head = blockIdx.y, b = blockIdx.z;
    const int head32 = head * 32;
    const int bML = b * MLOC, bMG = b * MG;
    uint32_t sb = smem_u32(sm);

    // stage Q (128 rows x 64B)
    {
        const __nv_bfloat16* qsrc = g_qb + ((size_t)(b * MQ + qtile * 128)) * 256 + head32;
#pragma unroll
        for (int i = 0; i < 4; i++) {
            int op = tid + i * 128;
            int rr = op >> 2, sg = op & 3;
            asm volatile("cp.async.cg.shared.global [%0], [%1], 16;"
                :: "r"(sb + QSM + rr * SROW + sg * 16), "l"(qsrc + (size_t)rr * 256 + sg * 8));
        }
        asm volatile("cp.async.commit_group;");
        asm volatile("cp.async.wait_group 0;" ::: "memory");
        __syncthreads();
    }
    uint32_t af[2][2][4];
#pragma unroll
    for (int mt = 0; mt < 2; mt++)
#pragma unroll
        for (int kt = 0; kt < 2; kt++)
            ldsm4(af[mt][kt], sb + QSM
                + (warp * 32 + mt * 16 + (lane & 7) + 8 * ((lane >> 3) & 1)) * SROW
                + kt * 32 + 16 * (lane >> 4));

    float o[2][4][4];
    float lsum[2][2];
#pragma unroll
    for (int i = 0; i < 2; i++) {
        lsum[i][0] = lsum[i][1] = 0.f;
#pragma unroll
        for (int j = 0; j < 4; j++)
#pragma unroll
            for (int t = 0; t < 4; t++) o[i][j][t] = 0.f;
    }

#define G_ISSUE(ch, buf) do {                                                             \
        int gk0_ = (ch) * 32;                                                             \
        _Pragma("unroll")                                                                 \
        for (int j_ = 0; j_ < 2; j_++) {                                                  \
            int idx_ = tid + j_ * 128;                                                    \
            int r_ = idx_ >> 3, s_ = idx_ & 7;                                            \
            uint32_t dst_ = sb + GSM + (buf) * 5120 +                                     \
                (s_ < 4 ? r_ * SROW + s_ * 16 : 2560 + r_ * SROW + (s_ - 4) * 16);        \
            const __nv_bfloat16* src_ = g_kvbm + ((size_t)(bMG + gk0_ + r_)) * 512        \
                + head32 + (s_ < 4 ? s_ * 8 : 256 + (s_ - 4) * 8);                        \
            asm volatile("cp.async.cg.shared.global [%0], [%1], 16;" :: "r"(dst_), "l"(src_)); \
        }                                                                                 \
        asm volatile("cp.async.commit_group;");                                          \
    } while (0)

#define L_ISSUE(win, lc, buf) do {                                                        \
        _Pragma("unroll")                                                                 \
        for (int j_ = 0; j_ < 8; j_++) {                                                  \
            int idx_ = lane + j_ * 32;                                                    \
            int r_ = idx_ >> 3, s_ = idx_ & 7;                                            \
            uint32_t dst_ = sb + LSM + warp * 10240 + (buf) * 5120 +                      \
                (s_ < 4 ? r_ * SROW + s_ * 16 : 2560 + r_ * SROW + (s_ - 4) * 16);        \
            const __nv_bfloat16* src_ = g_kvbl + ((size_t)(bML + (win) * 64 + (lc) * 32 + r_)) * 512 \
                + head32 + (s_ < 4 ? s_ * 8 : 256 + (s_ - 4) * 8);                        \
            asm volatile("cp.async.cg.shared.global [%0], [%1], 16;" :: "r"(dst_), "l"(src_)); \
        }                                                                                 \
        asm volatile("cp.async.commit_group;");                                          \
    } while (0)

    // prefetch global chunk 0 early, then do per-warp local windows
    G_ISSUE(0, 0);
    uint32_t lbase = sb + LSM + warp * 10240;
    int win0 = qtile * 8 + warp * 2;
    L_ISSUE(win0, 0, 0);
    L_ISSUE(win0, 1, 1);
    asm volatile("cp.async.wait_group 1;" ::: "memory"); __syncwarp();
    attn_chunk(lbase, lane, af, 0, 1, o, lsum);
    asm volatile("cp.async.wait_group 0;" ::: "memory"); __syncwarp();
    attn_chunk(lbase + 5120, lane, af, 0, 1, o, lsum);
    L_ISSUE(win0 + 1, 0, 0);
    L_ISSUE(win0 + 1, 1, 1);
    asm volatile("cp.async.wait_group 1;" ::: "memory"); __syncwarp();
    attn_chunk(lbase, lane, af, 1, 1, o, lsum);
    asm volatile("cp.async.wait_group 0;" ::: "memory"); __syncwarp();
    attn_chunk(lbase + 5120, lane, af, 1, 1, o, lsum);

    // global: 40 chunks of 32 keys, block-wide ping-pong
    for (int ch = 0; ch < 40; ch++) {
        if (ch + 1 < 40) {
            G_ISSUE(ch + 1, (ch + 1) & 1);
            asm volatile("cp.async.wait_group 1;" ::: "memory");
        } else {
            asm volatile("cp.async.wait_group 0;" ::: "memory");
        }
        __syncthreads();
        attn_chunk(sb + GSM + (ch & 1) * 5120, lane, af, 0, 2, o, lsum);
        __syncthreads();
    }

    // reduce l over quad lanes, normalize, store
#pragma unroll
    for (int mt = 0; mt < 2; mt++) {
        float l0 = lsum[mt][0], l1 = lsum[mt][1];
        l0 += __shfl_xor_sync(0xffffffffu, l0, 1);
        l0 += __shfl_xor_sync(0xffffffffu, l0, 2);
        l1 += __shfl_xor_sync(0xffffffffu, l1, 1);
        l1 += __shfl_xor_sync(0xffffffffu, l1, 2);
        float i0 = 1.f / l0, i1 = 1.f / l1;
        int row = qtile * 128 + warp * 32 + mt * 16 + (lane >> 2);
        size_t base = ((size_t)(b * MQ) + row) * 256 + head32 + 2 * (lane & 3);
#pragma unroll
        for (int nt = 0; nt < 4; nt++) {
            *(float2*)&g_ao[base + nt * 8] =
                make_float2(o[mt][nt][0] * i0, o[mt][nt][1] * i0);
            *(float2*)&g_ao[base + 8 * 256 + nt * 8] =
                make_float2(o[mt][nt][2] * i1, o[mt][nt][3] * i1);
        }
    }
}

// ---------------- 6) output projection + scatter + residual (FFMA2, proven) ----------------
__global__ void __launch_bounds__(256, 2) gemm_out(
    const float* __restrict__ feat, float* __restrict__ out,
    const float* __restrict__ Wm, const float* __restrict__ bias)
{
    const int m0 = blockIdx.x * 128, n0 = blockIdx.y * 128, b = blockIdx.z;
    const float* Ab = g_ao + (size_t)b * MQ * 256;
    __shared__ float As[16][129];
    __shared__ float Bs[16][128];
    const int tid = threadIdx.x;
    const int tx = tid & 15, ty = tid >> 4;
    u64 acc2[8][4];
#pragma unroll
    for (int i = 0; i < 8; i++)
#pragma unroll
        for (int j = 0; j < 4; j++) acc2[i][j] = 0ull;

    for (int k0 = 0; k0 < 256; k0 += 16) {
#pragma unroll
        for (int i = 0; i < 8; i++) {
            int flat = tid + i * 256;
            int mm = flat >> 4, kk = flat & 15;
            As[kk][mm] = Ab[(size_t)(m0 + mm) * 256 + k0 + kk];
        }
#pragma unroll
        for (int i = 0; i < 8; i++) {
            int flat = tid + i * 256;
            int kk = flat >> 7, nnq = flat & 127;
            Bs[kk][nnq] = Wm[(size_t)(k0 + kk) * 256 + n0 + nnq];
        }
        __syncthreads();
#pragma unroll
        for (int k = 0; k < 16; k++) {
            u64 b2[4];
#pragma unroll
            for (int jp = 0; jp < 4; jp++)
                b2[jp] = *(const u64*)&Bs[k][2 * tx + 32 * jp];
#pragma unroll
            for (int i = 0; i < 8; i++) {
                float a = As[k][ty * 8 + i];
                u64 a2 = pack2(a, a);
#pragma unroll
                for (int jp = 0; jp < 4; jp++)
                    acc2[i][jp] = ffma2(a2, b2[jp], acc2[i][jp]);
            }
        }
        __syncthreads();
    }
#pragma unroll
    for (int i = 0; i < 8; i++) {
        int q = m0 + ty * 8 + i;
        int w = q / 16, t = q % 16;
        int y = (w / 16) * 4 + t / 4;
        int x = (w % 16) * 4 + t % 4;
        int pix = y * 64 + x;
#pragma unroll
        for (int jp = 0; jp < 4; jp++) {
            int n = n0 + 2 * tx + 32 * jp;
            float c0, c1; unpack2(acc2[i][jp], c0, c1);
            size_t o0 = (((size_t)b * 256 + n) << 12) + pix;
            size_t o1 = o0 + 4096;
            out[o0] = c0 + bias[n] + feat[o0];
            out[o1] = c1 + bias[n + 1] + feat[o1];
        }
    }
}

// ---------------- launch (only harness pointers cross host->device) ----------------
extern "C" void kernel_launch(void* const* d_in, const int* in_sizes, int n_in,
                              void* d_out, int out_size) {
    const float* feat  = (const float*)d_in[0];
    const float* qkv_w = (const float*)d_in[1];
    const float* qkv_b = (const float*)d_in[2];
    const float* out_w = (const float*)d_in[3];
    const float* out_b = (const float*)d_in[4];
    const float* ln_w  = (const float*)d_in[5];
    const float* ln_b  = (const float*)d_in[6];
    float* out = (float*)d_out;

    cudaFuncSetAttribute(attn_mma, cudaFuncAttributeMaxDynamicSharedMemorySize, ATTN_SMEM);

    build_tq  <<<(B_ * MQ) / 8, 256>>>(feat, ln_w, ln_b);
    build_tloc<<<(int)(((size_t)B_ * MLOC * 256) / 256), 256>>>(feat);
    build_tmg <<<dim3(MG, B_), 256>>>(feat);
    build_wT  <<<768, 256>>>(qkv_w);

    gemm_all_mma<<<1232, 256>>>(qkv_b);

    attn_mma<<<dim3(32, 8, B_), 128, ATTN_SMEM>>>();

    gemm_out<<<dim3(MQ / 128, 256 / 128, B_), 256>>>(feat, out, out_w, out_b);
}

// round 17
// speedup vs baseline: 7.5085x; 1.2588x over previous
#include <cuda_runtime.h>
#include <cuda_bf16.h>
#include <cstdint>

#define B_   2
#define C_   256
#define MLOC 16384
#define MQ   4096
#define MG   1280
#define NW   256
#define LK   1344

typedef unsigned long long u64;

// ---------------- scratch (device globals; ONLY referenced from device code) ----------------
__device__ __nv_bfloat16 g_tq  [B_ * MQ * C_];
__device__ __nv_bfloat16 g_tloc[(size_t)B_ * MLOC * C_];
__device__ __nv_bfloat16 g_tmg [B_ * MG * C_];
__device__ __nv_bfloat16 g_wT  [768 * 256];           // qkv_w transposed: [n][k] bf16
__device__ __nv_bfloat16 g_owT [256 * 256];           // out_w transposed: [n][k] bf16
__device__ __nv_bfloat16 g_qb  [B_ * MQ * C_];        // Q (bias + scale*log2e folded), bf16
__device__ __nv_bfloat16 g_kvbl[(size_t)B_ * MLOC * 512];  // K:0..255 V:256..511 (bias incl), bf16
__device__ __nv_bfloat16 g_kvbm[B_ * MG * 512];
__device__ __nv_bfloat16 g_aob [B_ * MQ * C_];        // attention output, bf16

// Device-side pointer selection — NEVER pass __device__ symbols from host code
// (on GB300, host-shadow addresses are ATS-dereferenceable and fail silently).
__device__ __forceinline__ const __nv_bfloat16* in_ptr(int id) {
    switch (id) { case 0: return g_tq; case 1: return g_tloc; default: return g_tmg; }
}
__device__ __forceinline__ __nv_bfloat16* outb_ptr(int id) {
    switch (id) { case 0: return g_qb; case 1: return g_kvbl; default: return g_kvbm; }
}

// ---------------- misc primitives ----------------
__device__ __forceinline__ float ex2(float x) {
    float r; asm("ex2.approx.f32 %0, %1;" : "=f"(r) : "f"(x)); return r;
}
// pack two fp32 -> bf16x2 (lo = first arg)
__device__ __forceinline__ uint32_t cvtbf2(float lo, float hi) {
    uint32_t r; asm("cvt.rn.bf16x2.f32 %0, %1, %2;" : "=r"(r) : "f"(hi), "f"(lo)); return r;
}

// ---------------- baseline tensor-core primitives (sm_80+) ----------------
__device__ __forceinline__ uint32_t smem_u32(const void* p) {
    uint32_t a;
    asm("{ .reg .u64 t; cvta.to.shared.u64 t, %1; cvt.u32.u64 %0, t; }" : "=r"(a) : "l"(p));
    return a;
}
__device__ __forceinline__ void ldsm4(uint32_t* r, uint32_t addr) {
    asm volatile("ldmatrix.sync.aligned.m8n8.x4.shared.b16 {%0,%1,%2,%3}, [%4];"
                 : "=r"(r[0]), "=r"(r[1]), "=r"(r[2]), "=r"(r[3]) : "r"(addr));
}
__device__ __forceinline__ void ldsm4t(uint32_t* r, uint32_t addr) {
    asm volatile("ldmatrix.sync.aligned.m8n8.x4.trans.shared.b16 {%0,%1,%2,%3}, [%4];"
                 : "=r"(r[0]), "=r"(r[1]), "=r"(r[2]), "=r"(r[3]) : "r"(addr));
}
__device__ __forceinline__ void mma16816(float* d, const uint32_t* a, uint32_t b0, uint32_t b1) {
    asm volatile("mma.sync.aligned.m16n8k16.row.col.f32.bf16.bf16.f32 "
                 "{%0,%1,%2,%3}, {%4,%5,%6,%7}, {%8,%9}, {%0,%1,%2,%3};"
                 : "+f"(d[0]), "+f"(d[1]), "+f"(d[2]), "+f"(d[3])
                 : "r"(a[0]), "r"(a[1]), "r"(a[2]), "r"(a[3]), "r"(b0), "r"(b1));
}

// ---------------- 1) query tokens: gather + LayerNorm -> bf16 ----------------
__global__ void build_tq(const float* __restrict__ feat,
                         const float* __restrict__ lnw, const float* __restrict__ lnb) {
    int warp = threadIdx.x / 32, lane = threadIdx.x % 32;
    int qg = blockIdx.x * 8 + warp;
    int b = qg / MQ;
    int q = qg % MQ;
    int w = q / 16, t = q % 16;
    int wy = w / 16, wx = w % 16;
    float vals[8];
    float sum = 0.f;
#pragma unroll
    for (int i = 0; i < 8; i++) {
        int c  = lane + i * 32;
        int ch = t * 16 + c / 16;
        int iy = (c / 4) % 4;
        int ix = c % 4;
        int y  = wy * 4 + iy, x = wx * 4 + ix;
        float v = feat[(((size_t)b * 256 + ch) * 64 + y) * 64 + x];
        vals[i] = v; sum += v;
    }
#pragma unroll
    for (int o = 16; o; o >>= 1) sum += __shfl_xor_sync(0xffffffffu, sum, o);
    float mu = sum * (1.f / 256.f);
    float vs = 0.f;
#pragma unroll
    for (int i = 0; i < 8; i++) { float d = vals[i] - mu; vs += d * d; }
#pragma unroll
    for (int o = 16; o; o >>= 1) vs += __shfl_xor_sync(0xffffffffu, vs, o);
    float rstd = rsqrtf(vs * (1.f / 256.f) + 1e-5f);
#pragma unroll
    for (int i = 0; i < 8; i++) {
        int c = lane + i * 32;
        g_tq[(size_t)qg * 256 + c] = __float2bfloat16((vals[i] - mu) * rstd * lnw[c] + lnb[c]);
    }
}

// ---------------- 2) local tokens: gather (zero-padded) -> bf16 ----------------
__global__ void build_tloc(const float* __restrict__ feat) {
    int idx = blockIdx.x * 256 + threadIdx.x;
    int c   = idx % 256;
    int row = idx / 256;
    int b   = row / MLOC;
    int wt  = row % MLOC;
    int w   = wt / 64, t = wt % 64;
    int ch  = t * 4 + c / 64;
    int iy  = (c / 8) % 8;
    int ix  = c % 8;
    int y   = (w / 16) * 4 + iy - 2;
    int x   = (w % 16) * 4 + ix - 2;
    float v = 0.f;
    if ((unsigned)y < 64u && (unsigned)x < 64u)
        v = feat[(((size_t)b * 256 + ch) * 64 + y) * 64 + x];
    g_tloc[idx] = __float2bfloat16(v);
}

// ---------------- 3) mid/glb pooled tokens -> bf16 ----------------
__global__ void build_tmg(const float* __restrict__ feat) {
    int l = blockIdx.x, b = blockIdx.y, c = threadIdx.x;
    const float* f = feat + ((size_t)b * 256 + c) * 4096;
    float v;
    if (l < 1024) {
        int y = l / 32, x = l % 32;
        v = 0.25f * (f[(2 * y) * 64 + 2 * x]     + f[(2 * y) * 64 + 2 * x + 1] +
                     f[(2 * y + 1) * 64 + 2 * x] + f[(2 * y + 1) * 64 + 2 * x + 1]);
    } else {
        int g = l - 1024;
        int y = g / 16, x = g % 16;
        float s = 0.f;
#pragma unroll
        for (int dy = 0; dy < 4; dy++)
#pragma unroll
            for (int dx = 0; dx < 4; dx++) s += f[(4 * y + dy) * 64 + 4 * x + dx];
        v = 0.0625f * s;
    }
    g_tmg[((size_t)b * MG + l) * 256 + c] = __float2bfloat16(v);
}

// ---------------- 3b) transpose qkv_w and out_w -> bf16 [n][k] ----------------
__global__ void build_wT(const float* __restrict__ qkv_w, const float* __restrict__ out_w) {
    int idx = blockIdx.x * 256 + threadIdx.x;
    if (idx < 768 * 256) {
        int n = idx / 256, k = idx % 256;
        g_wT[idx] = __float2bfloat16(qkv_w[(size_t)k * 768 + n]);
    } else {
        int j = idx - 768 * 256;
        int n = j / 256, k = j % 256;
        g_owT[j] = __float2bfloat16(out_w[(size_t)k * 256 + n]);
    }
}

// ---------------- 4) projection GEMM via mma.sync bf16 (proven core; bf16 epilogue) ----------------
#define LDS_STRIDE 72
#define QSCL (0.17677669529663687f * 1.4426950408889634f)
__global__ void __launch_bounds__(256, 2) gemm_all_mma(const float* __restrict__ bias) {
    int id = blockIdx.x;
    int sel, Mrows, wcol0, ldc, nn;
    if (id < 1024)      { sel = 1; Mrows = MLOC; wcol0 = 256; ldc = 512; nn = 4; }
    else if (id < 1152) { sel = 0; id -= 1024; Mrows = MQ;  wcol0 = 0;   ldc = 256; nn = 2; }
    else                { sel = 2; id -= 1152; Mrows = MG;  wcol0 = 256; ldc = 512; nn = 4; }
    int per_b = (Mrows / 128) * nn;
    int b  = id / per_b;
    int r  = id % per_b;
    int m0 = (r / nn) * 128, n0 = (r % nn) * 128;

    __shared__ __align__(16) __nv_bfloat16 As[128 * LDS_STRIDE];
    __shared__ __align__(16) __nv_bfloat16 Bs[128 * LDS_STRIDE];

    const int tid = threadIdx.x;
    const int warp = tid >> 5, lane = tid & 31;
    const int wy = warp >> 1, wx = warp & 1;

    float acc[2][8][4];
#pragma unroll
    for (int i = 0; i < 2; i++)
#pragma unroll
        for (int j = 0; j < 8; j++)
#pragma unroll
            for (int t = 0; t < 4; t++) acc[i][j][t] = 0.f;

    const __nv_bfloat16* Asrc = in_ptr(sel) + ((size_t)b * Mrows + m0) * 256;
    const __nv_bfloat16* Bsrc = g_wT + (size_t)(wcol0 + n0) * 256;

    uint32_t as_base = smem_u32(As), bs_base = smem_u32(Bs);
    const int arow    = wy * 32 + (lane & 7) + ((lane >> 3) & 1) * 8;
    const int acolsel = (lane >> 4);
    const int brow    = wx * 64 + (lane & 7) + ((lane >> 4) & 1) * 8;
    const int bksel   = (lane >> 3) & 1;

    for (int kc = 0; kc < 4; kc++) {
#pragma unroll
        for (int i = 0; i < 4; i++) {
            int idx = tid + i * 256;
            int rr = idx >> 3, c8 = (idx & 7) * 8;
            *(uint4*)&As[rr * LDS_STRIDE + c8] = *(const uint4*)(Asrc + (size_t)rr * 256 + kc * 64 + c8);
            *(uint4*)&Bs[rr * LDS_STRIDE + c8] = *(const uint4*)(Bsrc + (size_t)rr * 256 + kc * 64 + c8);
        }
        __syncthreads();
#pragma unroll
        for (int ks = 0; ks < 4; ks++) {
            int kb = ks * 16;
            uint32_t af[2][4];
#pragma unroll
            for (int mt = 0; mt < 2; mt++)
                ldsm4(af[mt], as_base + ((arow + mt * 16) * LDS_STRIDE + kb + acolsel * 8) * 2);
            uint32_t bf[4][4];
#pragma unroll
            for (int p = 0; p < 4; p++)
                ldsm4(bf[p], bs_base + ((brow + p * 16) * LDS_STRIDE + kb + bksel * 8) * 2);
#pragma unroll
            for (int mt = 0; mt < 2; mt++)
#pragma unroll
                for (int p = 0; p < 4; p++) {
                    mma16816(acc[mt][2 * p],     af[mt], bf[p][0], bf[p][1]);
                    mma16816(acc[mt][2 * p + 1], af[mt], bf[p][2], bf[p][3]);
                }
        }
        __syncthreads();
    }

    __nv_bfloat16* obf = outb_ptr(sel);
    const float scl = (sel == 0) ? QSCL : 1.0f;
#pragma unroll
    for (int mt = 0; mt < 2; mt++) {
        int m = m0 + wy * 32 + mt * 16 + lane / 4;
#pragma unroll
        for (int nt = 0; nt < 8; nt++) {
            int n = n0 + wx * 64 + nt * 8 + 2 * (lane & 3);
            float2 bv = *(const float2*)&bias[wcol0 + n];
            *(uint32_t*)&obf[((size_t)b * Mrows + m) * ldc + n] =
                cvtbf2((acc[mt][nt][0] + bv.x) * scl, (acc[mt][nt][1] + bv.y) * scl);
            *(uint32_t*)&obf[((size_t)b * Mrows + m + 8) * ldc + n] =
                cvtbf2((acc[mt][nt][2] + bv.x) * scl, (acc[mt][nt][3] + bv.y) * scl);
        }
    }
}

// ---------------- 5) attention via mma.sync (FA2-style, direct softmax; R16-proven) ----------------
#define SROW 80
#define QSM  0
#define LSM  10240
#define GSM  51200
#define ATTN_SMEM 61440

__device__ __forceinline__ void attn_chunk(
    uint32_t ka, int lane, const uint32_t af[2][2][4],
    int mt0, int nmt, float o[2][4][4], float lsum[2][2])
{
    uint32_t va = ka + 2560;
    uint32_t bk[2][2][4];
#pragma unroll
    for (int h = 0; h < 2; h++)
#pragma unroll
        for (int ks = 0; ks < 2; ks++)
            ldsm4(bk[h][ks], ka + (h * 16 + (lane & 7) + 8 * ((lane >> 4) & 1)) * SROW
                               + ks * 32 + 16 * ((lane >> 3) & 1));
    uint32_t bv[2][2][4];
#pragma unroll
    for (int h = 0; h < 2; h++)
#pragma unroll
        for (int dh = 0; dh < 2; dh++)
            ldsm4t(bv[h][dh], va + (h * 16 + (lane & 7) + 8 * ((lane >> 3) & 1)) * SROW
                                + dh * 32 + 16 * ((lane >> 4) & 1));
#pragma unroll
    for (int mi = 0; mi < 2; mi++) {
        if (mi >= nmt) break;
        int mt = mt0 + mi;
        float c[4][4];
#pragma unroll
        for (int nt = 0; nt < 4; nt++)
#pragma unroll
            for (int t = 0; t < 4; t++) c[nt][t] = 0.f;
#pragma unroll
        for (int h = 0; h < 2; h++)
#pragma unroll
            for (int ks = 0; ks < 2; ks++) {
                mma16816(c[2 * h],     af[mt][ks], bk[h][ks][0], bk[h][ks][1]);
                mma16816(c[2 * h + 1], af[mt][ks], bk[h][ks][2], bk[h][ks][3]);
            }
#pragma unroll
        for (int nt = 0; nt < 4; nt++)
#pragma unroll
            for (int t = 0; t < 4; t++) {
                float e = ex2(c[nt][t]);
                lsum[mt][t >> 1] += e;
                c[nt][t] = e;
            }
#pragma unroll
        for (int h = 0; h < 2; h++) {
            uint32_t pa[4];
            pa[0] = cvtbf2(c[2 * h][0],     c[2 * h][1]);
            pa[1] = cvtbf2(c[2 * h][2],     c[2 * h][3]);
            pa[2] = cvtbf2(c[2 * h + 1][0], c[2 * h + 1][1]);
            pa[3] = cvtbf2(c[2 * h + 1][2], c[2 * h + 1][3]);
#pragma unroll
            for (int dh = 0; dh < 2; dh++) {
                mma16816(o[mt][2 * dh],     pa, bv[h][dh][0], bv[h][dh][1]);
                mma16816(o[mt][2 * dh + 1], pa, bv[h][dh][2], bv[h][dh][3]);
            }
        }
    }
}

__global__ void __launch_bounds__(128) attn_mma() {
    extern __shared__ __align__(16) char sm[];
    const int tid = threadIdx.x, warp = tid >> 5, lane = tid & 31;
    const int qtile = blockIdx.x, head = blockIdx.y, b = blockIdx.z;
    const int head32 = head * 32;
    const int bML = b * MLOC, bMG = b * MG;
    uint32_t sb = smem_u32(sm);

    {
        const __nv_bfloat16* qsrc = g_qb + ((size_t)(b * MQ + qtile * 128)) * 256 + head32;
#pragma unroll
        for (int i = 0; i < 4; i++) {
            int op = tid + i * 128;
            int rr = op >> 2, sg = op & 3;
            asm volatile("cp.async.cg.shared.global [%0], [%1], 16;"
                :: "r"(sb + QSM + rr * SROW + sg * 16), "l"(qsrc + (size_t)rr * 256 + sg * 8));
        }
        asm volatile("cp.async.commit_group;");
        asm volatile("cp.async.wait_group 0;" ::: "memory");
        __syncthreads();
    }
    uint32_t af[2][2][4];
#pragma unroll
    for (int mt = 0; mt < 2; mt++)
#pragma unroll
        for (int kt = 0; kt < 2; kt++)
            ldsm4(af[mt][kt], sb + QSM
                + (warp * 32 + mt * 16 + (lane & 7) + 8 * ((lane >> 3) & 1)) * SROW
                + kt * 32 + 16 * (lane >> 4));

    float o[2][4][4];
    float lsum[2][2];
#pragma unroll
    for (int i = 0; i < 2; i++) {
        lsum[i][0] = lsum[i][1] = 0.f;
#pragma unroll
        for (int j = 0; j < 4; j++)
#pragma unroll
            for (int t = 0; t < 4; t++) o[i][j][t] = 0.f;
    }

#define G_ISSUE(ch, buf) do {                                                             \
        int gk0_ = (ch) * 32;                                                             \
        _Pragma("unroll")                                                                 \
        for (int j_ = 0; j_ < 2; j_++) {                                                  \
            int idx_ = tid + j_ * 128;                                                    \
            int r_ = idx_ >> 3, s_ = idx_ & 7;                                            \
            uint32_t dst_ = sb + GSM + (buf) * 5120 +                                     \
                (s_ < 4 ? r_ * SROW + s_ * 16 : 2560 + r_ * SROW + (s_ - 4) * 16);        \
            const __nv_bfloat16* src_ = g_kvbm + ((size_t)(bMG + gk0_ + r_)) * 512        \
                + head32 + (s_ < 4 ? s_ * 8 : 256 + (s_ - 4) * 8);                        \
            asm volatile("cp.async.cg.shared.global [%0], [%1], 16;" :: "r"(dst_), "l"(src_)); \
        }                                                                                 \
        asm volatile("cp.async.commit_group;");                                          \
    } while (0)

#define L_ISSUE(win, lc, buf) do {                                                        \
        _Pragma("unroll")                                                                 \
        for (int j_ = 0; j_ < 8; j_++) {                                                  \
            int idx_ = lane + j_ * 32;                                                    \
            int r_ = idx_ >> 3, s_ = idx_ & 7;                                            \
            uint32_t dst_ = sb + LSM + warp * 10240 + (buf) * 5120 +                      \
                (s_ < 4 ? r_ * SROW + s_ * 16 : 2560 + r_ * SROW + (s_ - 4) * 16);        \
            const __nv_bfloat16* src_ = g_kvbl + ((size_t)(bML + (win) * 64 + (lc) * 32 + r_)) * 512 \
                + head32 + (s_ < 4 ? s_ * 8 : 256 + (s_ - 4) * 8);                        \
            asm volatile("cp.async.cg.shared.global [%0], [%1], 16;" :: "r"(dst_), "l"(src_)); \
        }                                                                                 \
        asm volatile("cp.async.commit_group;");                                          \
    } while (0)

    G_ISSUE(0, 0);
    uint32_t lbase = sb + LSM + warp * 10240;
    int win0 = qtile * 8 + warp * 2;
    L_ISSUE(win0, 0, 0);
    L_ISSUE(win0, 1, 1);
    asm volatile("cp.async.wait_group 1;" ::: "memory"); __syncwarp();
    attn_chunk(lbase, lane, af, 0, 1, o, lsum);
    asm volatile("cp.async.wait_group 0;" ::: "memory"); __syncwarp();
    attn_chunk(lbase + 5120, lane, af, 0, 1, o, lsum);
    L_ISSUE(win0 + 1, 0, 0);
    L_ISSUE(win0 + 1, 1, 1);
    asm volatile("cp.async.wait_group 1;" ::: "memory"); __syncwarp();
    attn_chunk(lbase, lane, af, 1, 1, o, lsum);
    asm volatile("cp.async.wait_group 0;" ::: "memory"); __syncwarp();
    attn_chunk(lbase + 5120, lane, af, 1, 1, o, lsum);

    for (int ch = 0; ch < 40; ch++) {
        if (ch + 1 < 40) {
            G_ISSUE(ch + 1, (ch + 1) & 1);
            asm volatile("cp.async.wait_group 1;" ::: "memory");
        } else {
            asm volatile("cp.async.wait_group 0;" ::: "memory");
        }
        __syncthreads();
        attn_chunk(sb + GSM + (ch & 1) * 5120, lane, af, 0, 2, o, lsum);
        __syncthreads();
    }

    // reduce l over quad lanes, normalize, store bf16
#pragma unroll
    for (int mt = 0; mt < 2; mt++) {
        float l0 = lsum[mt][0], l1 = lsum[mt][1];
        l0 += __shfl_xor_sync(0xffffffffu, l0, 1);
        l0 += __shfl_xor_sync(0xffffffffu, l0, 2);
        l1 += __shfl_xor_sync(0xffffffffu, l1, 1);
        l1 += __shfl_xor_sync(0xffffffffu, l1, 2);
        float i0 = 1.f / l0, i1 = 1.f / l1;
        int row = qtile * 128 + warp * 32 + mt * 16 + (lane >> 2);
        size_t base = ((size_t)(b * MQ) + row) * 256 + head32 + 2 * (lane & 3);
#pragma unroll
        for (int nt = 0; nt < 4; nt++) {
            *(uint32_t*)&g_aob[base + nt * 8] =
                cvtbf2(o[mt][nt][0] * i0, o[mt][nt][1] * i0);
            *(uint32_t*)&g_aob[base + 8 * 256 + nt * 8] =
                cvtbf2(o[mt][nt][2] * i1, o[mt][nt][3] * i1);
        }
    }
}

// ---------------- 6) output projection via mma.sync + scatter + residual ----------------
__global__ void __launch_bounds__(256, 2) gemm_out_mma(
    const float* __restrict__ feat, float* __restrict__ out,
    const float* __restrict__ bias)
{
    const int m0 = blockIdx.x * 128, n0 = blockIdx.y * 128, b = blockIdx.z;

    __shared__ __align__(16) __nv_bfloat16 As[128 * LDS_STRIDE];
    __shared__ __align__(16) __nv_bfloat16 Bs[128 * LDS_STRIDE];

    const int tid = threadIdx.x;
    const int warp = tid >> 5, lane = tid & 31;
    const int wy = warp >> 1, wx = warp & 1;

    float acc[2][8][4];
#pragma unroll
    for (int i = 0; i < 2; i++)
#pragma unroll
        for (int j = 0; j < 8; j++)
#pragma unroll
            for (int t = 0; t < 4; t++) acc[i][j][t] = 0.f;

    const __nv_bfloat16* Asrc = g_aob + ((size_t)b * MQ + m0) * 256;
    const __nv_bfloat16* Bsrc = g_owT + (size_t)n0 * 256;

    uint32_t as_base = smem_u32(As), bs_base = smem_u32(Bs);
    const int arow    = wy * 32 + (lane & 7) + ((lane >> 3) & 1) * 8;
    const int acolsel = (lane >> 4);
    const int brow    = wx * 64 + (lane & 7) + ((lane >> 4) & 1) * 8;
    const int bksel   = (lane >> 3) & 1;

    for (int kc = 0; kc < 4; kc++) {
#pragma unroll
        for (int i = 0; i < 4; i++) {
            int idx = tid + i * 256;
            int rr = idx >> 3, c8 = (idx & 7) * 8;
            *(uint4*)&As[rr * LDS_STRIDE + c8] = *(const uint4*)(Asrc + (size_t)rr * 256 + kc * 64 + c8);
            *(uint4*)&Bs[rr * LDS_STRIDE + c8] = *(const uint4*)(Bsrc + (size_t)rr * 256 + kc * 64 + c8);
        }
        __syncthreads();
#pragma unroll
        for (int ks = 0; ks < 4; ks++) {
            int kb = ks * 16;
            uint32_t af[2][4];
#pragma unroll
            for (int mt = 0; mt < 2; mt++)
                ldsm4(af[mt], as_base + ((arow + mt * 16) * LDS_STRIDE + kb + acolsel * 8) * 2);
            uint32_t bf[4][4];
#pragma unroll
            for (int p = 0; p < 4; p++)
                ldsm4(bf[p], bs_base + ((brow + p * 16) * LDS_STRIDE + kb + bksel * 8) * 2);
#pragma unroll
            for (int mt = 0; mt < 2; mt++)
#pragma unroll
                for (int p = 0; p < 4; p++) {
                    mma16816(acc[mt][2 * p],     af[mt], bf[p][0], bf[p][1]);
                    mma16816(acc[mt][2 * p + 1], af[mt], bf[p][2], bf[p][3]);
                }
        }
        __syncthreads();
    }

    // scatter epilogue: token -> pixel; fp32 bias + residual
#pragma unroll
    for (int mt = 0; mt < 2; mt++) {
        int m = m0 + wy * 32 + mt * 16 + lane / 4;
#pragma unroll
        for (int half = 0; half < 2; half++) {
            int q = m + half * 8;
            int w = q / 16, t = q % 16;
            int y = (w / 16) * 4 + t / 4;
            int x = (w % 16) * 4 + t % 4;
            int pix = y * 64 + x;
#pragma unroll
            for (int nt = 0; nt < 8; nt++) {
                int n = n0 + wx * 64 + nt * 8 + 2 * (lane & 3);
                float v0 = acc[mt][nt][2 * half], v1 = acc[mt][nt][2 * half + 1];
                size_t o0 = (((size_t)b * 256 + n) << 12) + pix;
                size_t o1 = o0 + 4096;
                out[o0] = v0 + bias[n] + feat[o0];
                out[o1] = v1 + bias[n + 1] + feat[o1];
            }
        }
    }
}

// ---------------- launch (only harness pointers cross host->device) ----------------
extern "C" void kernel_launch(void* const* d_in, const int* in_sizes, int n_in,
                              void* d_out, int out_size) {
    const float* feat  = (const float*)d_in[0];
    const float* qkv_w = (const float*)d_in[1];
    const float* qkv_b = (const float*)d_in[2];
    const float* out_w = (const float*)d_in[3];
    const float* out_b = (const float*)d_in[4];
    const float* ln_w  = (const float*)d_in[5];
    const float* ln_b  = (const float*)d_in[6];
    float* out = (float*)d_out;

    cudaFuncSetAttribute(attn_mma, cudaFuncAttributeMaxDynamicSharedMemorySize, ATTN_SMEM);

    build_tq  <<<(B_ * MQ) / 8, 256>>>(feat, ln_w, ln_b);
    build_tloc<<<(int)(((size_t)B_ * MLOC * 256) / 256), 256>>>(feat);
    build_tmg <<<dim3(MG, B_), 256>>>(feat);
    build_wT  <<<1024, 256>>>(qkv_w, out_w);

    gemm_all_mma<<<1232, 256>>>(qkv_b);

    attn_mma<<<dim3(32, 8, B_), 128, ATTN_SMEM>>>();

    gemm_out_mma<<<dim3(MQ / 128, 256 / 128, B_), 256>>>(feat, out, out_b);
}